// round 2
// baseline (speedup 1.0000x reference)
#include <cuda_runtime.h>
#include <math.h>

#define NN    50000
#define EE    500000
#define ET    550000          // EE + NN self-loops
#define FIN   128
#define HD1   256             // HEADS*HID
#define HEADS 8
#define HID   32
#define OUTC  64

// ---------------- scratch (static device allocations; no cudaMalloc) --------
__device__ float    g_h1[NN * HD1];     // layer1 projected features (pre-agg), later reused as ELU(out1+b1)
__device__ float    g_out1[NN * HD1];   // layer1 aggregated output
__device__ float    g_al1[NN * HEADS];
__device__ float    g_ar1[NN * HEADS];
__device__ unsigned g_max1[NN * HEADS]; // flipped-float max accumulator
__device__ float    g_maxf1[NN * HEADS];
__device__ float    g_den1[NN * HEADS];

__device__ float    g_h2[NN * OUTC];
__device__ float    g_out2[NN * OUTC];
__device__ float    g_al2[NN];
__device__ float    g_ar2[NN];
__device__ unsigned g_max2[NN];
__device__ float    g_maxf2[NN];
__device__ float    g_den2[NN];

// ---------------- helpers ---------------------------------------------------
__device__ __forceinline__ unsigned flip_f(float f) {
    unsigned u = __float_as_uint(f);
    return u ^ ((u >> 31) ? 0xFFFFFFFFu : 0x80000000u);
}
__device__ __forceinline__ float unflip_f(unsigned u) {
    return __uint_as_float(u ^ ((u >> 31) ? 0x80000000u : 0xFFFFFFFFu));
}
__device__ __forceinline__ float lrelu(float v) { return v > 0.f ? v : 0.2f * v; }

__device__ __forceinline__ void atomic_add4(float4* p, float4 v) {
#if defined(__CUDA_ARCH__) && (__CUDA_ARCH__ >= 900) && (CUDART_VERSION >= 12080)
    atomicAdd(p, v);
#else
    float* f = (float*)p;
    atomicAdd(f + 0, v.x); atomicAdd(f + 1, v.y);
    atomicAdd(f + 2, v.z); atomicAdd(f + 3, v.w);
#endif
}
__device__ __forceinline__ void atomic_add2(float2* p, float2 v) {
#if defined(__CUDA_ARCH__) && (__CUDA_ARCH__ >= 900) && (CUDART_VERSION >= 12080)
    atomicAdd(p, v);
#else
    float* f = (float*)p;
    atomicAdd(f + 0, v.x); atomicAdd(f + 1, v.y);
#endif
}

__device__ __forceinline__ void edge_sd(const int* __restrict__ ei, int e, int& s, int& d) {
    if (e < EE) { s = ei[e]; d = ei[EE + e]; }
    else        { s = e - EE; d = s; }
}

// ---------------- init ------------------------------------------------------
__global__ void k_init() {
    int i = blockIdx.x * blockDim.x + threadIdx.x;
    int stride = gridDim.x * blockDim.x;
    for (int idx = i; idx < NN * HD1; idx += stride) g_out1[idx] = 0.f;
    for (int idx = i; idx < NN * OUTC; idx += stride) g_out2[idx] = 0.f;
    for (int idx = i; idx < NN * HEADS; idx += stride) { g_den1[idx] = 0.f; g_max1[idx] = 0u; }
    for (int idx = i; idx < NN; idx += stride) { g_den2[idx] = 0.f; g_max2[idx] = 0u; }
}

// ---------------- SGEMM: C[nrows,ncols] = A[nrows,K] @ B[K,ncols] -----------
// tile: 32 rows x 64 cols per block, 256 threads, each thread 2 rows x 4 cols.
// K processed in chunks of 128. Requires K % 128 == 0, ncols % 64 == 0.
__global__ __launch_bounds__(256) void k_gemm(
    const float* __restrict__ A, const float* __restrict__ B, float* __restrict__ C,
    int nrows, int K, int ncols)
{
    __shared__ float Bs[128 * 64];
    __shared__ float As[32 * 128];
    int tid = threadIdx.x;
    int j0 = tid & 15;       // 0..15
    int r0 = tid >> 4;       // 0..15
    int colBase = blockIdx.y * 64;
    int rowBase = blockIdx.x * 32;

    float acc[2][4] = {{0.f, 0.f, 0.f, 0.f}, {0.f, 0.f, 0.f, 0.f}};

    for (int kc = 0; kc < K; kc += 128) {
        for (int idx = tid; idx < 128 * 64; idx += 256) {
            int k = idx >> 6, j = idx & 63;
            Bs[idx] = B[(kc + k) * ncols + colBase + j];
        }
        for (int idx = tid; idx < 32 * 128; idx += 256) {
            int r = idx >> 7, k = idx & 127;
            int row = rowBase + r;
            As[idx] = (row < nrows) ? A[row * K + kc + k] : 0.f;
        }
        __syncthreads();
        #pragma unroll 8
        for (int k = 0; k < 128; ++k) {
            float a0 = As[r0 * 128 + k];
            float a1 = As[(r0 + 16) * 128 + k];
            float b0 = Bs[k * 64 + j0];
            float b1 = Bs[k * 64 + j0 + 16];
            float b2 = Bs[k * 64 + j0 + 32];
            float b3 = Bs[k * 64 + j0 + 48];
            acc[0][0] += a0 * b0; acc[0][1] += a0 * b1;
            acc[0][2] += a0 * b2; acc[0][3] += a0 * b3;
            acc[1][0] += a1 * b0; acc[1][1] += a1 * b1;
            acc[1][2] += a1 * b2; acc[1][3] += a1 * b3;
        }
        __syncthreads();
    }
    #pragma unroll
    for (int rr = 0; rr < 2; ++rr) {
        int row = rowBase + r0 + rr * 16;
        if (row < nrows) {
            #pragma unroll
            for (int jj = 0; jj < 4; ++jj)
                C[row * ncols + colBase + j0 + jj * 16] = acc[rr][jj];
        }
    }
}

// ---------------- layer-1 attention logits (warp per node) ------------------
__global__ __launch_bounds__(256) void k_logits1(
    const float* __restrict__ a_src, const float* __restrict__ a_dst)
{
    int warp = threadIdx.x >> 5, lane = threadIdx.x & 31;
    int n = blockIdx.x * 8 + warp;
    if (n >= NN) return;
    const float* hrow = g_h1 + n * HD1;
    int h = lane >> 2;                 // lanes 4h..4h+3 cover head h
    float sa = 0.f, sd = 0.f;
    int c0 = lane * 8;
    #pragma unroll
    for (int i = 0; i < 8; ++i) {
        int c = c0 + i;
        float v = hrow[c];
        int cc = c & 31;
        sa += v * a_src[h * HID + cc];
        sd += v * a_dst[h * HID + cc];
    }
    sa += __shfl_xor_sync(0xffffffffu, sa, 1);
    sa += __shfl_xor_sync(0xffffffffu, sa, 2);
    sd += __shfl_xor_sync(0xffffffffu, sd, 1);
    sd += __shfl_xor_sync(0xffffffffu, sd, 2);
    if ((lane & 3) == 0) { g_al1[n * HEADS + h] = sa; g_ar1[n * HEADS + h] = sd; }
}

// ---------------- layer-1 edge passes ---------------------------------------
__global__ __launch_bounds__(256) void k_emax1(const int* __restrict__ ei) {
    int e = blockIdx.x * blockDim.x + threadIdx.x;
    if (e >= ET) return;
    int s, d; edge_sd(ei, e, s, d);
    const float4* As = (const float4*)(g_al1 + s * HEADS);
    const float4* Ad = (const float4*)(g_ar1 + d * HEADS);
    float4 a0 = As[0], a1 = As[1], b0 = Ad[0], b1 = Ad[1];
    float v[8] = {a0.x + b0.x, a0.y + b0.y, a0.z + b0.z, a0.w + b0.w,
                  a1.x + b1.x, a1.y + b1.y, a1.z + b1.z, a1.w + b1.w};
    unsigned* mrow = g_max1 + d * HEADS;
    #pragma unroll
    for (int h = 0; h < 8; ++h) atomicMax(&mrow[h], flip_f(lrelu(v[h])));
}

__global__ void k_unflip1() {
    int i = blockIdx.x * blockDim.x + threadIdx.x;
    if (i < NN * HEADS) g_maxf1[i] = unflip_f(g_max1[i]);
}

__global__ __launch_bounds__(256) void k_esum1(const int* __restrict__ ei) {
    int e = blockIdx.x * blockDim.x + threadIdx.x;
    if (e >= ET) return;
    int s, d; edge_sd(ei, e, s, d);
    const float4* As = (const float4*)(g_al1 + s * HEADS);
    const float4* Ad = (const float4*)(g_ar1 + d * HEADS);
    const float4* Am = (const float4*)(g_maxf1 + d * HEADS);
    float4 a0 = As[0], a1 = As[1], b0 = Ad[0], b1 = Ad[1];
    float4 m0 = Am[0], m1 = Am[1];
    float v[8] = {a0.x + b0.x, a0.y + b0.y, a0.z + b0.z, a0.w + b0.w,
                  a1.x + b1.x, a1.y + b1.y, a1.z + b1.z, a1.w + b1.w};
    float m[8] = {m0.x, m0.y, m0.z, m0.w, m1.x, m1.y, m1.z, m1.w};
    float* drow = g_den1 + d * HEADS;
    #pragma unroll
    for (int h = 0; h < 8; ++h) atomicAdd(&drow[h], expf(lrelu(v[h]) - m[h]));
}

// warp per edge; lane covers channels [8*lane, 8*lane+8) => head = lane>>2
__global__ __launch_bounds__(256) void k_aggr1(const int* __restrict__ ei) {
    int lane = threadIdx.x & 31;
    int e = (blockIdx.x * blockDim.x + threadIdx.x) >> 5;
    if (e >= ET) return;
    int s, d; edge_sd(ei, e, s, d);
    int h = lane >> 2;
    float v = lrelu(g_al1[s * HEADS + h] + g_ar1[d * HEADS + h]);
    float alpha = expf(v - g_maxf1[d * HEADS + h]) / (g_den1[d * HEADS + h] + 1e-16f);
    const float4* hs = (const float4*)(g_h1 + s * HD1);
    float4* od = (float4*)(g_out1 + d * HD1);
    float4 x0 = hs[lane * 2], x1 = hs[lane * 2 + 1];
    x0.x *= alpha; x0.y *= alpha; x0.z *= alpha; x0.w *= alpha;
    x1.x *= alpha; x1.y *= alpha; x1.z *= alpha; x1.w *= alpha;
    atomic_add4(od + lane * 2, x0);
    atomic_add4(od + lane * 2 + 1, x1);
}

// ---------------- bias + ELU (writes back into g_h1) ------------------------
__global__ void k_biaselu(const float* __restrict__ b1) {
    int i = blockIdx.x * blockDim.x + threadIdx.x;
    int stride = gridDim.x * blockDim.x;
    for (int idx = i; idx < NN * HD1; idx += stride) {
        float v = g_out1[idx] + b1[idx & (HD1 - 1)];
        g_h1[idx] = v > 0.f ? v : expm1f(v);
    }
}

// ---------------- layer-2 attention logits (warp per node) ------------------
__global__ __launch_bounds__(256) void k_logits2(
    const float* __restrict__ a_src, const float* __restrict__ a_dst)
{
    int warp = threadIdx.x >> 5, lane = threadIdx.x & 31;
    int n = blockIdx.x * 8 + warp;
    if (n >= NN) return;
    float2 v = ((const float2*)(g_h2 + n * OUTC))[lane];
    int c = lane * 2;
    float sa = v.x * a_src[c] + v.y * a_src[c + 1];
    float sd = v.x * a_dst[c] + v.y * a_dst[c + 1];
    #pragma unroll
    for (int off = 16; off > 0; off >>= 1) {
        sa += __shfl_xor_sync(0xffffffffu, sa, off);
        sd += __shfl_xor_sync(0xffffffffu, sd, off);
    }
    if (lane == 0) { g_al2[n] = sa; g_ar2[n] = sd; }
}

// ---------------- layer-2 edge passes ---------------------------------------
__global__ __launch_bounds__(256) void k_emax2(const int* __restrict__ ei) {
    int e = blockIdx.x * blockDim.x + threadIdx.x;
    if (e >= ET) return;
    int s, d; edge_sd(ei, e, s, d);
    float v = lrelu(g_al2[s] + g_ar2[d]);
    atomicMax(&g_max2[d], flip_f(v));
}

__global__ void k_unflip2() {
    int i = blockIdx.x * blockDim.x + threadIdx.x;
    if (i < NN) g_maxf2[i] = unflip_f(g_max2[i]);
}

__global__ __launch_bounds__(256) void k_esum2(const int* __restrict__ ei) {
    int e = blockIdx.x * blockDim.x + threadIdx.x;
    if (e >= ET) return;
    int s, d; edge_sd(ei, e, s, d);
    float v = lrelu(g_al2[s] + g_ar2[d]);
    atomicAdd(&g_den2[d], expf(v - g_maxf2[d]));
}

__global__ __launch_bounds__(256) void k_aggr2(const int* __restrict__ ei) {
    int lane = threadIdx.x & 31;
    int e = (blockIdx.x * blockDim.x + threadIdx.x) >> 5;
    if (e >= ET) return;
    int s, d; edge_sd(ei, e, s, d);
    float v = lrelu(g_al2[s] + g_ar2[d]);
    float alpha = expf(v - g_maxf2[d]) / (g_den2[d] + 1e-16f);
    float2 x = ((const float2*)(g_h2 + s * OUTC))[lane];
    x.x *= alpha; x.y *= alpha;
    atomic_add2(((float2*)(g_out2 + d * OUTC)) + lane, x);
}

// ---------------- bias + log_softmax (warp per node) ------------------------
__global__ __launch_bounds__(256) void k_final(
    const float* __restrict__ b2, float* __restrict__ out)
{
    int warp = threadIdx.x >> 5, lane = threadIdx.x & 31;
    int n = blockIdx.x * 8 + warp;
    if (n >= NN) return;
    float2 v = ((const float2*)(g_out2 + n * OUTC))[lane];
    int c = lane * 2;
    v.x += b2[c]; v.y += b2[c + 1];
    float m = fmaxf(v.x, v.y);
    #pragma unroll
    for (int off = 16; off > 0; off >>= 1)
        m = fmaxf(m, __shfl_xor_sync(0xffffffffu, m, off));
    float ssum = expf(v.x - m) + expf(v.y - m);
    #pragma unroll
    for (int off = 16; off > 0; off >>= 1)
        ssum += __shfl_xor_sync(0xffffffffu, ssum, off);
    float l = m + logf(ssum);
    out[n * OUTC + c] = v.x - l;
    out[n * OUTC + c + 1] = v.y - l;
}

// ---------------- launcher ---------------------------------------------------
extern "C" void kernel_launch(void* const* d_in, const int* in_sizes, int n_in,
                              void* d_out, int out_size)
{
    const float* x   = (const float*)d_in[0];
    const int*   ei  = (const int*)d_in[1];
    const float* W1  = (const float*)d_in[2];
    const float* a1s = (const float*)d_in[3];
    const float* a1d = (const float*)d_in[4];
    const float* b1  = (const float*)d_in[5];
    const float* W2  = (const float*)d_in[6];
    const float* a2s = (const float*)d_in[7];
    const float* a2d = (const float*)d_in[8];
    const float* b2  = (const float*)d_in[9];
    float* out = (float*)d_out;

    float *h1p, *h2p;
    cudaGetSymbolAddress((void**)&h1p, g_h1);
    cudaGetSymbolAddress((void**)&h2p, g_h2);

    const int EB = (ET + 255) / 256;          // thread-per-edge blocks
    const int EWB = (ET + 7) / 8;             // warp-per-edge blocks (8 warps/block)
    const int NWB = (NN + 7) / 8;             // warp-per-node blocks

    k_init<<<4096, 256>>>();

    // ---- layer 1 ----
    dim3 g1((NN + 31) / 32, HD1 / 64);
    k_gemm<<<g1, 256>>>(x, W1, h1p, NN, FIN, HD1);
    k_logits1<<<NWB, 256>>>(a1s, a1d);
    k_emax1<<<EB, 256>>>(ei);
    k_unflip1<<<(NN * HEADS + 255) / 256, 256>>>();
    k_esum1<<<EB, 256>>>(ei);
    k_aggr1<<<EWB, 256>>>(ei);
    k_biaselu<<<4096, 256>>>(b1);

    // ---- layer 2 ----
    dim3 g2((NN + 31) / 32, OUTC / 64);
    k_gemm<<<g2, 256>>>(h1p, W2, h2p, NN, HD1, OUTC);
    k_logits2<<<NWB, 256>>>(a2s, a2d);
    k_emax2<<<EB, 256>>>(ei);
    k_unflip2<<<(NN + 255) / 256, 256>>>();
    k_esum2<<<EB, 256>>>(ei);
    k_aggr2<<<EWB, 256>>>(ei);
    k_final<<<NWB, 256>>>(b2, out);
}

// round 3
// speedup vs baseline: 2.0230x; 2.0230x over previous
#include <cuda_runtime.h>
#include <math.h>

#define NN    50000
#define EE    500000
#define ET    550000          // EE + NN self-loops
#define FIN   128
#define HD1   256             // HEADS*HID
#define HEADS 8
#define HID   32
#define OUTC  64
#define NBLK  196             // ceil(NN/256) for scan

// ---------------- scratch (static device arrays; no cudaMalloc) -------------
__device__ float g_h1 [NN * HD1];    // gemm1 output (projected features)
__device__ float g_h1b[NN * HD1];    // layer-1 GAT output after bias+ELU
__device__ float g_al1[NN * HEADS];
__device__ float g_ar1[NN * HEADS];
__device__ float g_h2 [NN * OUTC];   // gemm2 output
__device__ float g_al2[NN];
__device__ float g_ar2[NN];

__device__ int g_deg  [NN];
__device__ int g_cur  [NN];
__device__ int g_start[NN];
__device__ int g_scan [NN];
__device__ int g_bsum [256];
__device__ int g_bsum2[256];
__device__ int g_esrc [ET];          // CSR-by-dst: src node of each edge

// ---------------- helpers ---------------------------------------------------
__device__ __forceinline__ float lrelu(float v) { return v > 0.f ? v : 0.2f * v; }

__device__ __forceinline__ int edge_dst(const int* __restrict__ ei, int e) {
    return (e < EE) ? ei[EE + e] : (e - EE);
}
__device__ __forceinline__ int edge_src(const int* __restrict__ ei, int e) {
    return (e < EE) ? ei[e] : (e - EE);
}

// ---------------- CSR build --------------------------------------------------
__global__ void k_zero() {
    int i = blockIdx.x * blockDim.x + threadIdx.x;
    if (i < NN) { g_deg[i] = 0; g_cur[i] = 0; }
}

__global__ void k_hist(const int* __restrict__ ei) {
    int e = blockIdx.x * blockDim.x + threadIdx.x;
    if (e >= ET) return;
    atomicAdd(&g_deg[edge_dst(ei, e)], 1);
}

__global__ void k_scanA() {
    __shared__ int s[256];
    int i = blockIdx.x * 256 + threadIdx.x;
    int v = (i < NN) ? g_deg[i] : 0;
    s[threadIdx.x] = v;
    __syncthreads();
    #pragma unroll
    for (int off = 1; off < 256; off <<= 1) {
        int t = (threadIdx.x >= off) ? s[threadIdx.x - off] : 0;
        __syncthreads();
        s[threadIdx.x] += t;
        __syncthreads();
    }
    if (i < NN) g_scan[i] = s[threadIdx.x];
    if (threadIdx.x == 255) g_bsum[blockIdx.x] = s[255];
}

__global__ void k_scanB() {
    __shared__ int s[256];
    int v = (threadIdx.x < NBLK) ? g_bsum[threadIdx.x] : 0;
    s[threadIdx.x] = v;
    __syncthreads();
    #pragma unroll
    for (int off = 1; off < 256; off <<= 1) {
        int t = (threadIdx.x >= off) ? s[threadIdx.x - off] : 0;
        __syncthreads();
        s[threadIdx.x] += t;
        __syncthreads();
    }
    g_bsum2[threadIdx.x] = s[threadIdx.x] - v;   // exclusive
}

__global__ void k_scanC() {
    int i = blockIdx.x * 256 + threadIdx.x;
    if (i < NN) g_start[i] = g_scan[i] - g_deg[i] + g_bsum2[blockIdx.x];
}

__global__ void k_scatter(const int* __restrict__ ei) {
    int e = blockIdx.x * blockDim.x + threadIdx.x;
    if (e >= ET) return;
    int d = edge_dst(ei, e);
    int pos = g_start[d] + atomicAdd(&g_cur[d], 1);
    g_esrc[pos] = edge_src(ei, e);
}

// ---------------- SGEMM: C = A[nrows,K] @ B[K,ncols] -------------------------
// 64x64 tile, 256 threads, 4x4 microtile, K-chunk 16, float4 LDS.
__global__ __launch_bounds__(256) void k_gemm(
    const float* __restrict__ A, const float* __restrict__ B, float* __restrict__ C,
    int nrows, int K, int ncols)
{
    __shared__ float As[16][68];
    __shared__ float Bs[16][68];
    int tid = threadIdx.x;
    int tx = tid & 15, ty = tid >> 4;
    int rowBase = blockIdx.x * 64;
    int colBase = blockIdx.y * 64;

    float acc[4][4] = {};

    int ar = tid >> 2;                 // 0..63 : A row within tile
    int akq = (tid & 3) * 4;           // 0,4,8,12 : A k-quad
    int bk = tid >> 4;                 // 0..15 : B k
    int bc = (tid & 15) * 4;           // 0..60 : B col quad

    for (int kc = 0; kc < K; kc += 16) {
        int grow = rowBase + ar;
        float4 av = make_float4(0.f, 0.f, 0.f, 0.f);
        if (grow < nrows)
            av = *(const float4*)(A + grow * K + kc + akq);
        As[akq + 0][ar] = av.x;
        As[akq + 1][ar] = av.y;
        As[akq + 2][ar] = av.z;
        As[akq + 3][ar] = av.w;
        float4 bv = *(const float4*)(B + (kc + bk) * ncols + colBase + bc);
        *(float4*)&Bs[bk][bc] = bv;
        __syncthreads();
        #pragma unroll
        for (int k = 0; k < 16; ++k) {
            float4 a = *(const float4*)&As[k][ty * 4];
            float4 b = *(const float4*)&Bs[k][tx * 4];
            acc[0][0] += a.x * b.x; acc[0][1] += a.x * b.y; acc[0][2] += a.x * b.z; acc[0][3] += a.x * b.w;
            acc[1][0] += a.y * b.x; acc[1][1] += a.y * b.y; acc[1][2] += a.y * b.z; acc[1][3] += a.y * b.w;
            acc[2][0] += a.z * b.x; acc[2][1] += a.z * b.y; acc[2][2] += a.z * b.z; acc[2][3] += a.z * b.w;
            acc[3][0] += a.w * b.x; acc[3][1] += a.w * b.y; acc[3][2] += a.w * b.z; acc[3][3] += a.w * b.w;
        }
        __syncthreads();
    }
    #pragma unroll
    for (int i = 0; i < 4; ++i) {
        int row = rowBase + ty * 4 + i;
        if (row < nrows) {
            float4 v = make_float4(acc[i][0], acc[i][1], acc[i][2], acc[i][3]);
            *(float4*)(C + row * ncols + colBase + tx * 4) = v;
        }
    }
}

// ---------------- layer-1 attention logits (warp per node) ------------------
__global__ __launch_bounds__(256) void k_logits1(
    const float* __restrict__ a_src, const float* __restrict__ a_dst)
{
    int warp = threadIdx.x >> 5, lane = threadIdx.x & 31;
    int n = blockIdx.x * 8 + warp;
    if (n >= NN) return;
    const float* hrow = g_h1 + n * HD1;
    int h = lane >> 2;
    float sa = 0.f, sd = 0.f;
    int c0 = lane * 8;
    #pragma unroll
    for (int i = 0; i < 8; ++i) {
        int c = c0 + i;
        float v = hrow[c];
        int cc = c & 31;
        sa += v * a_src[h * HID + cc];
        sd += v * a_dst[h * HID + cc];
    }
    sa += __shfl_xor_sync(0xffffffffu, sa, 1);
    sa += __shfl_xor_sync(0xffffffffu, sa, 2);
    sd += __shfl_xor_sync(0xffffffffu, sd, 1);
    sd += __shfl_xor_sync(0xffffffffu, sd, 2);
    if ((lane & 3) == 0) { g_al1[n * HEADS + h] = sa; g_ar1[n * HEADS + h] = sd; }
}

// ---------------- fused layer-1 GAT: max -> weighted gather -> bias+ELU -----
// warp per destination node; lane covers channels [8*lane, 8*lane+8), head=lane>>2
__global__ __launch_bounds__(256) void k_gat1(const float* __restrict__ b1) {
    int warp = threadIdx.x >> 5, lane = threadIdx.x & 31;
    int n = blockIdx.x * 8 + warp;
    if (n >= NN) return;
    int beg = g_start[n], deg = g_deg[n];
    int h = lane >> 2;
    float ard = g_ar1[n * HEADS + h];

    // phase 1: per-head max (4 lanes of each head split the edges)
    float mx = -1e30f;
    for (int i = (lane & 3); i < deg; i += 4) {
        int s = g_esrc[beg + i];
        mx = fmaxf(mx, lrelu(g_al1[s * HEADS + h] + ard));
    }
    mx = fmaxf(mx, __shfl_xor_sync(0xffffffffu, mx, 1));
    mx = fmaxf(mx, __shfl_xor_sync(0xffffffffu, mx, 2));

    // phase 2: weighted gather + denominator in one pass
    float sum = 0.f;
    float4 acc0 = make_float4(0.f, 0.f, 0.f, 0.f);
    float4 acc1 = make_float4(0.f, 0.f, 0.f, 0.f);
    for (int i = 0; i < deg; ++i) {
        int s = g_esrc[beg + i];
        float v = lrelu(g_al1[s * HEADS + h] + ard);
        float p = __expf(v - mx);
        sum += p;
        const float4* hp = (const float4*)(g_h1 + s * HD1) + lane * 2;
        float4 x0 = hp[0], x1 = hp[1];
        acc0.x += p * x0.x; acc0.y += p * x0.y; acc0.z += p * x0.z; acc0.w += p * x0.w;
        acc1.x += p * x1.x; acc1.y += p * x1.y; acc1.z += p * x1.z; acc1.w += p * x1.w;
    }
    float r = 1.f / (sum + 1e-16f);
    int c = lane * 8;
    float o[8] = {acc0.x * r, acc0.y * r, acc0.z * r, acc0.w * r,
                  acc1.x * r, acc1.y * r, acc1.z * r, acc1.w * r};
    float w[8];
    #pragma unroll
    for (int j = 0; j < 8; ++j) {
        float t = o[j] + b1[c + j];
        w[j] = t > 0.f ? t : expm1f(t);
    }
    float4* dst = (float4*)(g_h1b + n * HD1 + c);
    dst[0] = make_float4(w[0], w[1], w[2], w[3]);
    dst[1] = make_float4(w[4], w[5], w[6], w[7]);
}

// ---------------- layer-2 attention logits (warp per node) ------------------
__global__ __launch_bounds__(256) void k_logits2(
    const float* __restrict__ a_src, const float* __restrict__ a_dst)
{
    int warp = threadIdx.x >> 5, lane = threadIdx.x & 31;
    int n = blockIdx.x * 8 + warp;
    if (n >= NN) return;
    float2 v = ((const float2*)(g_h2 + n * OUTC))[lane];
    int c = lane * 2;
    float sa = v.x * a_src[c] + v.y * a_src[c + 1];
    float sd = v.x * a_dst[c] + v.y * a_dst[c + 1];
    #pragma unroll
    for (int off = 16; off > 0; off >>= 1) {
        sa += __shfl_xor_sync(0xffffffffu, sa, off);
        sd += __shfl_xor_sync(0xffffffffu, sd, off);
    }
    if (lane == 0) { g_al2[n] = sa; g_ar2[n] = sd; }
}

// ---------------- fused layer-2 GAT + bias + log-softmax --------------------
__global__ __launch_bounds__(256) void k_gat2(
    const float* __restrict__ b2, float* __restrict__ out)
{
    int warp = threadIdx.x >> 5, lane = threadIdx.x & 31;
    int n = blockIdx.x * 8 + warp;
    if (n >= NN) return;
    int beg = g_start[n], deg = g_deg[n];
    float ard = g_ar2[n];

    float mx = -1e30f;
    for (int i = lane; i < deg; i += 32) {
        int s = g_esrc[beg + i];
        mx = fmaxf(mx, lrelu(g_al2[s] + ard));
    }
    #pragma unroll
    for (int off = 16; off > 0; off >>= 1)
        mx = fmaxf(mx, __shfl_xor_sync(0xffffffffu, mx, off));

    float sum = 0.f;
    float2 acc = make_float2(0.f, 0.f);
    for (int i = 0; i < deg; ++i) {
        int s = g_esrc[beg + i];
        float v = lrelu(g_al2[s] + ard);
        float p = __expf(v - mx);
        sum += p;
        float2 x = ((const float2*)(g_h2 + s * OUTC))[lane];
        acc.x += p * x.x;
        acc.y += p * x.y;
    }
    float r = 1.f / (sum + 1e-16f);
    int c = lane * 2;
    float v0 = acc.x * r + b2[c];
    float v1 = acc.y * r + b2[c + 1];

    // warp log-softmax over 64 values (2 per lane)
    float m = fmaxf(v0, v1);
    #pragma unroll
    for (int off = 16; off > 0; off >>= 1)
        m = fmaxf(m, __shfl_xor_sync(0xffffffffu, m, off));
    float ss = expf(v0 - m) + expf(v1 - m);
    #pragma unroll
    for (int off = 16; off > 0; off >>= 1)
        ss += __shfl_xor_sync(0xffffffffu, ss, off);
    float l = m + logf(ss);
    out[n * OUTC + c]     = v0 - l;
    out[n * OUTC + c + 1] = v1 - l;
}

// ---------------- launcher ---------------------------------------------------
extern "C" void kernel_launch(void* const* d_in, const int* in_sizes, int n_in,
                              void* d_out, int out_size)
{
    const float* x   = (const float*)d_in[0];
    const int*   ei  = (const int*)d_in[1];
    const float* W1  = (const float*)d_in[2];
    const float* a1s = (const float*)d_in[3];
    const float* a1d = (const float*)d_in[4];
    const float* b1  = (const float*)d_in[5];
    const float* W2  = (const float*)d_in[6];
    const float* a2s = (const float*)d_in[7];
    const float* a2d = (const float*)d_in[8];
    const float* b2  = (const float*)d_in[9];
    float* out = (float*)d_out;

    float *h1p, *h1bp, *h2p;
    cudaGetSymbolAddress((void**)&h1p,  g_h1);
    cudaGetSymbolAddress((void**)&h1bp, g_h1b);
    cudaGetSymbolAddress((void**)&h2p,  g_h2);

    const int EB  = (ET + 255) / 256;
    const int NB  = (NN + 255) / 256;
    const int NWB = (NN + 7) / 8;

    // CSR build (shared by both layers)
    k_zero<<<NB, 256>>>();
    k_hist<<<EB, 256>>>(ei);
    k_scanA<<<NBLK, 256>>>();
    k_scanB<<<1, 256>>>();
    k_scanC<<<NBLK, 256>>>();
    k_scatter<<<EB, 256>>>(ei);

    // ---- layer 1 ----
    dim3 g1((NN + 63) / 64, HD1 / 64);
    k_gemm<<<g1, 256>>>(x, W1, h1p, NN, FIN, HD1);
    k_logits1<<<NWB, 256>>>(a1s, a1d);
    k_gat1<<<NWB, 256>>>(b1);

    // ---- layer 2 ----
    dim3 g2((NN + 63) / 64, OUTC / 64);
    k_gemm<<<g2, 256>>>(h1bp, W2, h2p, NN, HD1, OUTC);
    k_logits2<<<NWB, 256>>>(a2s, a2d);
    k_gat2<<<NWB, 256>>>(b2, out);
}

// round 5
// speedup vs baseline: 2.1488x; 1.0622x over previous
#include <cuda_runtime.h>
#include <math.h>

#define NN    50000
#define EE    500000
#define ET    550000          // EE + NN self-loops
#define FIN   128
#define HD1   256             // HEADS*HID
#define HEADS 8
#define HID   32
#define OUTC  64
#define NBLK  196             // ceil(NN/256)

typedef unsigned long long ull;

// ---------------- scratch (static device arrays; no cudaMalloc) -------------
__device__ float g_h1 [NN * HD1];    // gemm1 output
__device__ float g_h1b[NN * HD1];    // layer-1 GAT output (post bias+ELU)
__device__ float g_al1[NN * HEADS];
__device__ float g_ar1[NN * HEADS];
__device__ float g_h2 [NN * OUTC];
__device__ float g_al2[NN];
__device__ float g_ar2[NN];

__device__ int g_deg  [NN];
__device__ int g_cur  [NN];
__device__ int g_start[NN];
__device__ int g_scan [NN];
__device__ int g_bsum [256];
__device__ int g_esrc [ET];

// ---------------- helpers ---------------------------------------------------
__device__ __forceinline__ float lrelu(float v) { return v > 0.f ? v : 0.2f * v; }

__device__ __forceinline__ int edge_dst(const int* __restrict__ ei, int e) {
    return (e < EE) ? ei[EE + e] : (e - EE);
}
__device__ __forceinline__ int edge_src(const int* __restrict__ ei, int e) {
    return (e < EE) ? ei[e] : (e - EE);
}

__device__ __forceinline__ ull f2dup(float v) {
    ull r; asm("mov.b64 %0, {%1, %1};" : "=l"(r) : "f"(v)); return r;
}
__device__ __forceinline__ void fma2(ull& c, ull a, ull b) {
#if defined(__CUDA_ARCH__) && (__CUDA_ARCH__ >= 1000)
    asm("fma.rn.f32x2 %0, %1, %2, %3;" : "=l"(c) : "l"(a), "l"(b), "l"(c));
#else
    float2 cf, af, bf;
    asm("mov.b64 {%0, %1}, %2;" : "=f"(cf.x), "=f"(cf.y) : "l"(c));
    asm("mov.b64 {%0, %1}, %2;" : "=f"(af.x), "=f"(af.y) : "l"(a));
    asm("mov.b64 {%0, %1}, %2;" : "=f"(bf.x), "=f"(bf.y) : "l"(b));
    cf.x = fmaf(af.x, bf.x, cf.x);
    cf.y = fmaf(af.y, bf.y, cf.y);
    asm("mov.b64 %0, {%1, %2};" : "=l"(c) : "f"(cf.x), "f"(cf.y));
#endif
}
__device__ __forceinline__ float2 f2unpack(ull v) {
    float2 r; asm("mov.b64 {%0, %1}, %2;" : "=f"(r.x), "=f"(r.y) : "l"(v)); return r;
}

// ---------------- CSR build --------------------------------------------------
__global__ void k_zero() {
    int i = blockIdx.x * blockDim.x + threadIdx.x;
    if (i < NN) { g_deg[i] = 0; g_cur[i] = 0; }
}

__global__ void k_hist(const int* __restrict__ ei) {
    int e = blockIdx.x * blockDim.x + threadIdx.x;
    if (e >= ET) return;
    atomicAdd(&g_deg[edge_dst(ei, e)], 1);
}

__global__ void k_scanA() {
    __shared__ int s[256];
    int i = blockIdx.x * 256 + threadIdx.x;
    int v = (i < NN) ? g_deg[i] : 0;
    s[threadIdx.x] = v;
    __syncthreads();
    #pragma unroll
    for (int off = 1; off < 256; off <<= 1) {
        int t = (threadIdx.x >= off) ? s[threadIdx.x - off] : 0;
        __syncthreads();
        s[threadIdx.x] += t;
        __syncthreads();
    }
    if (i < NN) g_scan[i] = s[threadIdx.x];
    if (threadIdx.x == 255) g_bsum[blockIdx.x] = s[255];
}

// per-block: sum bsum[j<blockIdx] inline, then start = scan - deg + offset
__global__ void k_scanC() {
    __shared__ int red[256];
    int tid = threadIdx.x;
    red[tid] = (tid < (int)blockIdx.x) ? g_bsum[tid] : 0;
    __syncthreads();
    #pragma unroll
    for (int off = 128; off > 0; off >>= 1) {
        if (tid < off) red[tid] += red[tid + off];
        __syncthreads();
    }
    int base = red[0];
    int i = blockIdx.x * 256 + tid;
    if (i < NN) g_start[i] = g_scan[i] - g_deg[i] + base;
}

__global__ void k_scatter(const int* __restrict__ ei) {
    int e = blockIdx.x * blockDim.x + threadIdx.x;
    if (e >= ET) return;
    int d = edge_dst(ei, e);
    int pos = g_start[d] + atomicAdd(&g_cur[d], 1);
    g_esrc[pos] = edge_src(ei, e);
}

// ---------------- SGEMM with packed f32x2 FMA --------------------------------
// tile: 128 rows x (16*NR) cols, 256 threads, 8 x NR microtile, K-chunk 16.
template<int NR>
__global__ __launch_bounds__(256) void k_gemm(
    const float* __restrict__ A, const float* __restrict__ B, float* __restrict__ C,
    int nrows, int K, int ncols)
{
    constexpr int TN = 16 * NR;
    constexpr int KC = 16;
    __shared__ float As[KC][128 + 4];
    __shared__ float Bs[KC][TN + 4];
    int tid = threadIdx.x;
    int tx = tid & 15, ty = tid >> 4;
    int rowBase = blockIdx.x * 128;
    int colBase = blockIdx.y * TN;

    ull acc[8][NR / 2];
    #pragma unroll
    for (int i = 0; i < 8; ++i)
        #pragma unroll
        for (int j = 0; j < NR / 2; ++j) acc[i][j] = 0ull;

    int arow = tid >> 2;            // 0..63
    int ak4  = (tid & 3) * 4;       // 0,4,8,12

    for (int kc = 0; kc < K; kc += KC) {
        #pragma unroll
        for (int rr = 0; rr < 2; ++rr) {
            int r = arow + rr * 64;
            int grow = rowBase + r;
            float4 av = make_float4(0.f, 0.f, 0.f, 0.f);
            if (grow < nrows) av = *(const float4*)(A + (size_t)grow * K + kc + ak4);
            As[ak4 + 0][r] = av.x;
            As[ak4 + 1][r] = av.y;
            As[ak4 + 2][r] = av.z;
            As[ak4 + 3][r] = av.w;
        }
        #pragma unroll
        for (int idx = tid; idx < KC * (TN / 4); idx += 256) {
            int k = idx / (TN / 4), cq = idx % (TN / 4);
            float4 bv = *(const float4*)(B + (size_t)(kc + k) * ncols + colBase + cq * 4);
            *(float4*)&Bs[k][cq * 4] = bv;
        }
        __syncthreads();
        #pragma unroll
        for (int k = 0; k < KC; ++k) {
            float4 aA = *(const float4*)&As[k][ty * 8];
            float4 aB = *(const float4*)&As[k][ty * 8 + 4];
            float a[8] = {aA.x, aA.y, aA.z, aA.w, aB.x, aB.y, aB.z, aB.w};
            ull b[NR / 2];
            const ulonglong2* bp = (const ulonglong2*)&Bs[k][tx * NR];
            #pragma unroll
            for (int j = 0; j < NR / 4; ++j) {
                ulonglong2 t = bp[j];
                b[j * 2] = t.x; b[j * 2 + 1] = t.y;
            }
            #pragma unroll
            for (int i = 0; i < 8; ++i) {
                ull aa = f2dup(a[i]);
                #pragma unroll
                for (int j = 0; j < NR / 2; ++j) fma2(acc[i][j], aa, b[j]);
            }
        }
        __syncthreads();
    }
    #pragma unroll
    for (int i = 0; i < 8; ++i) {
        int row = rowBase + ty * 8 + i;
        if (row < nrows) {
            float* cp = C + (size_t)row * ncols + colBase + tx * NR;
            #pragma unroll
            for (int j = 0; j < NR / 4; ++j) {
                float2 u0 = f2unpack(acc[i][j * 2]);
                float2 u1 = f2unpack(acc[i][j * 2 + 1]);
                *(float4*)(cp + j * 4) = make_float4(u0.x, u0.y, u1.x, u1.y);
            }
        }
    }
}

// ---------------- layer-1 attention logits (warp per node) ------------------
__global__ __launch_bounds__(256) void k_logits1(
    const float* __restrict__ a_src, const float* __restrict__ a_dst)
{
    int warp = threadIdx.x >> 5, lane = threadIdx.x & 31;
    int n = blockIdx.x * 8 + warp;
    if (n >= NN) return;
    const float* hrow = g_h1 + (size_t)n * HD1;
    int h = lane >> 2;
    float sa = 0.f, sd = 0.f;
    int c0 = lane * 8;
    #pragma unroll
    for (int i = 0; i < 8; ++i) {
        int c = c0 + i;
        float v = hrow[c];
        int cc = c & 31;
        sa += v * a_src[h * HID + cc];
        sd += v * a_dst[h * HID + cc];
    }
    sa += __shfl_xor_sync(0xffffffffu, sa, 1);
    sa += __shfl_xor_sync(0xffffffffu, sa, 2);
    sd += __shfl_xor_sync(0xffffffffu, sd, 1);
    sd += __shfl_xor_sync(0xffffffffu, sd, 2);
    if ((lane & 3) == 0) { g_al1[n * HEADS + h] = sa; g_ar1[n * HEADS + h] = sd; }
}

// ---------------- fused layer-1 GAT -----------------------------------------
__global__ __launch_bounds__(256) void k_gat1(const float* __restrict__ b1) {
    int warp = threadIdx.x >> 5, lane = threadIdx.x & 31;
    int n = blockIdx.x * 8 + warp;
    if (n >= NN) return;
    int beg = g_start[n], deg = g_deg[n];
    int h = lane >> 2;
    float ard = g_ar1[n * HEADS + h];

    float mx = -1e30f;
    for (int i = (lane & 3); i < deg; i += 4) {
        int s = g_esrc[beg + i];
        mx = fmaxf(mx, lrelu(g_al1[s * HEADS + h] + ard));
    }
    mx = fmaxf(mx, __shfl_xor_sync(0xffffffffu, mx, 1));
    mx = fmaxf(mx, __shfl_xor_sync(0xffffffffu, mx, 2));

    float sum = 0.f;
    float4 acc0 = make_float4(0.f, 0.f, 0.f, 0.f);
    float4 acc1 = make_float4(0.f, 0.f, 0.f, 0.f);
    int i = 0;
    for (; i + 2 <= deg; i += 2) {
        int s0 = g_esrc[beg + i];
        int s1 = g_esrc[beg + i + 1];
        float v0 = lrelu(g_al1[s0 * HEADS + h] + ard);
        float v1 = lrelu(g_al1[s1 * HEADS + h] + ard);
        float p0 = __expf(v0 - mx);
        float p1 = __expf(v1 - mx);
        sum += p0 + p1;
        const float4* h0 = (const float4*)(g_h1 + (size_t)s0 * HD1) + lane * 2;
        const float4* h1 = (const float4*)(g_h1 + (size_t)s1 * HD1) + lane * 2;
        float4 x00 = h0[0], x01 = h0[1], x10 = h1[0], x11 = h1[1];
        acc0.x += p0 * x00.x + p1 * x10.x; acc0.y += p0 * x00.y + p1 * x10.y;
        acc0.z += p0 * x00.z + p1 * x10.z; acc0.w += p0 * x00.w + p1 * x10.w;
        acc1.x += p0 * x01.x + p1 * x11.x; acc1.y += p0 * x01.y + p1 * x11.y;
        acc1.z += p0 * x01.z + p1 * x11.z; acc1.w += p0 * x01.w + p1 * x11.w;
    }
    if (i < deg) {
        int s0 = g_esrc[beg + i];
        float v0 = lrelu(g_al1[s0 * HEADS + h] + ard);
        float p0 = __expf(v0 - mx);
        sum += p0;
        const float4* h0 = (const float4*)(g_h1 + (size_t)s0 * HD1) + lane * 2;
        float4 x00 = h0[0], x01 = h0[1];
        acc0.x += p0 * x00.x; acc0.y += p0 * x00.y; acc0.z += p0 * x00.z; acc0.w += p0 * x00.w;
        acc1.x += p0 * x01.x; acc1.y += p0 * x01.y; acc1.z += p0 * x01.z; acc1.w += p0 * x01.w;
    }
    float r = 1.f / (sum + 1e-16f);
    int c = lane * 8;
    float o[8] = {acc0.x * r, acc0.y * r, acc0.z * r, acc0.w * r,
                  acc1.x * r, acc1.y * r, acc1.z * r, acc1.w * r};
    float w[8];
    #pragma unroll
    for (int j = 0; j < 8; ++j) {
        float t = o[j] + b1[c + j];
        w[j] = t > 0.f ? t : expm1f(t);
    }
    float4* dst = (float4*)(g_h1b + (size_t)n * HD1 + c);
    dst[0] = make_float4(w[0], w[1], w[2], w[3]);
    dst[1] = make_float4(w[4], w[5], w[6], w[7]);
}

// ---------------- layer-2 attention logits ----------------------------------
__global__ __launch_bounds__(256) void k_logits2(
    const float* __restrict__ a_src, const float* __restrict__ a_dst)
{
    int warp = threadIdx.x >> 5, lane = threadIdx.x & 31;
    int n = blockIdx.x * 8 + warp;
    if (n >= NN) return;
    float2 v = ((const float2*)(g_h2 + (size_t)n * OUTC))[lane];
    int c = lane * 2;
    float sa = v.x * a_src[c] + v.y * a_src[c + 1];
    float sd = v.x * a_dst[c] + v.y * a_dst[c + 1];
    #pragma unroll
    for (int off = 16; off > 0; off >>= 1) {
        sa += __shfl_xor_sync(0xffffffffu, sa, off);
        sd += __shfl_xor_sync(0xffffffffu, sd, off);
    }
    if (lane == 0) { g_al2[n] = sa; g_ar2[n] = sd; }
}

// ---------------- fused layer-2 GAT + bias + log-softmax --------------------
__global__ __launch_bounds__(256) void k_gat2(
    const float* __restrict__ b2, float* __restrict__ out)
{
    int warp = threadIdx.x >> 5, lane = threadIdx.x & 31;
    int n = blockIdx.x * 8 + warp;
    if (n >= NN) return;
    int beg = g_start[n], deg = g_deg[n];
    float ard = g_ar2[n];

    float mx = -1e30f;
    for (int i = lane; i < deg; i += 32) {
        int s = g_esrc[beg + i];
        mx = fmaxf(mx, lrelu(g_al2[s] + ard));
    }
    #pragma unroll
    for (int off = 16; off > 0; off >>= 1)
        mx = fmaxf(mx, __shfl_xor_sync(0xffffffffu, mx, off));

    float sum = 0.f;
    float2 acc = make_float2(0.f, 0.f);
    int i = 0;
    for (; i + 2 <= deg; i += 2) {
        int s0 = g_esrc[beg + i];
        int s1 = g_esrc[beg + i + 1];
        float v0 = lrelu(g_al2[s0] + ard);
        float v1 = lrelu(g_al2[s1] + ard);
        float p0 = __expf(v0 - mx);
        float p1 = __expf(v1 - mx);
        sum += p0 + p1;
        float2 x0 = ((const float2*)(g_h2 + (size_t)s0 * OUTC))[lane];
        float2 x1 = ((const float2*)(g_h2 + (size_t)s1 * OUTC))[lane];
        acc.x += p0 * x0.x + p1 * x1.x;
        acc.y += p0 * x0.y + p1 * x1.y;
    }
    if (i < deg) {
        int s0 = g_esrc[beg + i];
        float v0 = lrelu(g_al2[s0] + ard);
        float p0 = __expf(v0 - mx);
        sum += p0;
        float2 x0 = ((const float2*)(g_h2 + (size_t)s0 * OUTC))[lane];
        acc.x += p0 * x0.x;
        acc.y += p0 * x0.y;
    }
    float r = 1.f / (sum + 1e-16f);
    int c = lane * 2;
    float v0 = acc.x * r + b2[c];
    float v1 = acc.y * r + b2[c + 1];

    float m = fmaxf(v0, v1);
    #pragma unroll
    for (int off = 16; off > 0; off >>= 1)
        m = fmaxf(m, __shfl_xor_sync(0xffffffffu, m, off));
    float ss = expf(v0 - m) + expf(v1 - m);
    #pragma unroll
    for (int off = 16; off > 0; off >>= 1)
        ss += __shfl_xor_sync(0xffffffffu, ss, off);
    float l = m + logf(ss);
    out[(size_t)n * OUTC + c]     = v0 - l;
    out[(size_t)n * OUTC + c + 1] = v1 - l;
}

// ---------------- launcher ---------------------------------------------------
extern "C" void kernel_launch(void* const* d_in, const int* in_sizes, int n_in,
                              void* d_out, int out_size)
{
    const float* x   = (const float*)d_in[0];
    const int*   ei  = (const int*)d_in[1];
    const float* W1  = (const float*)d_in[2];
    const float* a1s = (const float*)d_in[3];
    const float* a1d = (const float*)d_in[4];
    const float* b1  = (const float*)d_in[5];
    const float* W2  = (const float*)d_in[6];
    const float* a2s = (const float*)d_in[7];
    const float* a2d = (const float*)d_in[8];
    const float* b2  = (const float*)d_in[9];
    float* out = (float*)d_out;

    float *h1p, *h1bp, *h2p;
    cudaGetSymbolAddress((void**)&h1p,  g_h1);
    cudaGetSymbolAddress((void**)&h1bp, g_h1b);
    cudaGetSymbolAddress((void**)&h2p,  g_h2);

    const int EB  = (ET + 255) / 256;
    const int NB  = (NN + 255) / 256;
    const int NWB = (NN + 7) / 8;

    // CSR build
    k_zero<<<NB, 256>>>();
    k_hist<<<EB, 256>>>(ei);
    k_scanA<<<NBLK, 256>>>();
    k_scanC<<<NBLK, 256>>>();
    k_scatter<<<EB, 256>>>(ei);

    // ---- layer 1 ----
    dim3 g1((NN + 127) / 128, HD1 / 128);
    k_gemm<8><<<g1, 256>>>(x, W1, h1p, NN, FIN, HD1);
    k_logits1<<<NWB, 256>>>(a1s, a1d);
    k_gat1<<<NWB, 256>>>(b1);

    // ---- layer 2 ----
    dim3 g2((NN + 127) / 128, 1);
    k_gemm<4><<<g2, 256>>>(h1bp, W2, h2p, NN, HD1, OUTC);
    k_logits2<<<NWB, 256>>>(a2s, a2d);
    k_gat2<<<NWB, 256>>>(b2, out);
}

// round 6
// speedup vs baseline: 2.3914x; 1.1129x over previous
#include <cuda_runtime.h>
#include <math.h>

#define NN    50000
#define EE    500000
#define ET    550000          // EE + NN self-loops
#define FIN   128
#define HD1   256             // HEADS*HID
#define HEADS 8
#define HID   32
#define OUTC  64
#define NBLK  196             // ceil(NN/256)

// ---------------- scratch (static device arrays; no cudaMalloc) -------------
__device__ float g_h1 [NN * HD1];    // gemm1 output
__device__ float g_h1b[NN * HD1];    // layer-1 GAT output (post bias+ELU)
__device__ float g_al1[NN * HEADS];
__device__ float g_ar1[NN * HEADS];
__device__ float g_h2 [NN * OUTC];
__device__ float g_al2[NN];
__device__ float g_ar2[NN];

__device__ int g_deg  [NN];
__device__ int g_cur  [NN];
__device__ int g_start[NN];
__device__ int g_scan [NN];
__device__ int g_bsum [256];
__device__ int g_esrc [ET];

// ---------------- helpers ---------------------------------------------------
__device__ __forceinline__ float lrelu(float v) { return v > 0.f ? v : 0.2f * v; }

__device__ __forceinline__ int edge_dst(const int* __restrict__ ei, int e) {
    return (e < EE) ? ei[EE + e] : (e - EE);
}
__device__ __forceinline__ int edge_src(const int* __restrict__ ei, int e) {
    return (e < EE) ? ei[e] : (e - EE);
}

__device__ __forceinline__ unsigned cvt_tf32(float x) {
    unsigned r; asm("cvt.rna.tf32.f32 %0, %1;" : "=r"(r) : "f"(x)); return r;
}

__device__ __forceinline__ void mma_tf32(float c[4], const unsigned a[4], const unsigned b[2]) {
    asm volatile(
        "mma.sync.aligned.m16n8k8.row.col.f32.tf32.tf32.f32 "
        "{%0,%1,%2,%3}, {%4,%5,%6,%7}, {%8,%9}, {%0,%1,%2,%3};"
        : "+f"(c[0]), "+f"(c[1]), "+f"(c[2]), "+f"(c[3])
        : "r"(a[0]), "r"(a[1]), "r"(a[2]), "r"(a[3]), "r"(b[0]), "r"(b[1]));
}

// ---------------- CSR build --------------------------------------------------
__global__ void k_zero() {
    int i = blockIdx.x * blockDim.x + threadIdx.x;
    if (i < NN) { g_deg[i] = 0; g_cur[i] = 0; }
}

__global__ void k_hist(const int* __restrict__ ei) {
    int e = blockIdx.x * blockDim.x + threadIdx.x;
    if (e >= ET) return;
    atomicAdd(&g_deg[edge_dst(ei, e)], 1);
}

__global__ void k_scanA() {
    __shared__ int s[256];
    int i = blockIdx.x * 256 + threadIdx.x;
    int v = (i < NN) ? g_deg[i] : 0;
    s[threadIdx.x] = v;
    __syncthreads();
    #pragma unroll
    for (int off = 1; off < 256; off <<= 1) {
        int t = (threadIdx.x >= off) ? s[threadIdx.x - off] : 0;
        __syncthreads();
        s[threadIdx.x] += t;
        __syncthreads();
    }
    if (i < NN) g_scan[i] = s[threadIdx.x];
    if (threadIdx.x == 255) g_bsum[blockIdx.x] = s[255];
}

// per-block: sum bsum[j<blockIdx] inline, then start = scan - deg + offset
__global__ void k_scanC() {
    __shared__ int red[256];
    int tid = threadIdx.x;
    red[tid] = (tid < (int)blockIdx.x) ? g_bsum[tid] : 0;
    __syncthreads();
    #pragma unroll
    for (int off = 128; off > 0; off >>= 1) {
        if (tid < off) red[tid] += red[tid + off];
        __syncthreads();
    }
    int base = red[0];
    int i = blockIdx.x * 256 + tid;
    if (i < NN) g_start[i] = g_scan[i] - g_deg[i] + base;
}

__global__ void k_scatter(const int* __restrict__ ei) {
    int e = blockIdx.x * blockDim.x + threadIdx.x;
    if (e >= ET) return;
    int d = edge_dst(ei, e);
    int pos = g_start[d] + atomicAdd(&g_cur[d], 1);
    g_esrc[pos] = edge_src(ei, e);
}

// ---------------- TF32 tensor-core GEMM: C = A[M,K] @ B[K,N] -----------------
// block: 128 rows x 64 cols, 256 threads = 8 warps (4 m-warps x 2 n-warps),
// warp tile 32x32 = 2x4 mma tiles of m16n8k8. BK = 8.
__global__ __launch_bounds__(256) void k_gemm_tf32(
    const float* __restrict__ A, const float* __restrict__ B, float* __restrict__ C,
    int nrows, int K, int ncols)
{
    __shared__ unsigned As[128 * 8];     // [row][k]
    __shared__ unsigned Bs[8 * 68];      // [k][n], padded row 68
    int tid = threadIdx.x;
    int lane = tid & 31, warp = tid >> 5;
    int g = lane >> 2, tig = lane & 3;   // group id / thread-in-group
    int wm = warp & 3, wn = warp >> 2;
    int rowBase = blockIdx.x * 128, colBase = blockIdx.y * 64;

    float c[2][4][4];
    #pragma unroll
    for (int mt = 0; mt < 2; ++mt)
        #pragma unroll
        for (int nt = 0; nt < 4; ++nt)
            #pragma unroll
            for (int r = 0; r < 4; ++r) c[mt][nt][r] = 0.f;

    int ar = tid >> 1;              // 0..127
    int ak = (tid & 1) * 4;         // 0 or 4

    for (int kc = 0; kc < K; kc += 8) {
        int grow = rowBase + ar;
        float4 av = make_float4(0.f, 0.f, 0.f, 0.f);
        if (grow < nrows) av = *(const float4*)(A + (size_t)grow * K + kc + ak);
        unsigned* ap = As + ar * 8 + ak;
        ap[0] = cvt_tf32(av.x); ap[1] = cvt_tf32(av.y);
        ap[2] = cvt_tf32(av.z); ap[3] = cvt_tf32(av.w);
        if (tid < 128) {
            int bk = tid >> 4, bn = (tid & 15) * 4;
            float4 bv = *(const float4*)(B + (size_t)(kc + bk) * ncols + colBase + bn);
            unsigned* bp = Bs + bk * 68 + bn;
            bp[0] = cvt_tf32(bv.x); bp[1] = cvt_tf32(bv.y);
            bp[2] = cvt_tf32(bv.z); bp[3] = cvt_tf32(bv.w);
        }
        __syncthreads();

        unsigned a[2][4], b[4][2];
        #pragma unroll
        for (int mt = 0; mt < 2; ++mt) {
            int r = wm * 32 + mt * 16;
            a[mt][0] = As[(r + g) * 8 + tig];
            a[mt][1] = As[(r + 8 + g) * 8 + tig];
            a[mt][2] = As[(r + g) * 8 + tig + 4];
            a[mt][3] = As[(r + 8 + g) * 8 + tig + 4];
        }
        #pragma unroll
        for (int nt = 0; nt < 4; ++nt) {
            int cn = wn * 32 + nt * 8 + g;
            b[nt][0] = Bs[tig * 68 + cn];
            b[nt][1] = Bs[(tig + 4) * 68 + cn];
        }
        #pragma unroll
        for (int mt = 0; mt < 2; ++mt)
            #pragma unroll
            for (int nt = 0; nt < 4; ++nt)
                mma_tf32(c[mt][nt], a[mt], b[nt]);
        __syncthreads();
    }

    #pragma unroll
    for (int mt = 0; mt < 2; ++mt) {
        #pragma unroll
        for (int nt = 0; nt < 4; ++nt) {
            int row0 = rowBase + wm * 32 + mt * 16 + g;
            int col  = colBase + wn * 32 + nt * 8 + tig * 2;
            if (row0 < nrows)
                *(float2*)(C + (size_t)row0 * ncols + col) = make_float2(c[mt][nt][0], c[mt][nt][1]);
            int row1 = row0 + 8;
            if (row1 < nrows)
                *(float2*)(C + (size_t)row1 * ncols + col) = make_float2(c[mt][nt][2], c[mt][nt][3]);
        }
    }
}

// ---------------- layer-1 attention logits (warp per node) ------------------
__global__ __launch_bounds__(256) void k_logits1(
    const float* __restrict__ a_src, const float* __restrict__ a_dst)
{
    int warp = threadIdx.x >> 5, lane = threadIdx.x & 31;
    int n = blockIdx.x * 8 + warp;
    if (n >= NN) return;
    const float* hrow = g_h1 + (size_t)n * HD1;
    int h = lane >> 2;
    float sa = 0.f, sd = 0.f;
    int c0 = lane * 8;
    #pragma unroll
    for (int i = 0; i < 8; ++i) {
        int c = c0 + i;
        float v = hrow[c];
        int cc = c & 31;
        sa += v * a_src[h * HID + cc];
        sd += v * a_dst[h * HID + cc];
    }
    sa += __shfl_xor_sync(0xffffffffu, sa, 1);
    sa += __shfl_xor_sync(0xffffffffu, sa, 2);
    sd += __shfl_xor_sync(0xffffffffu, sd, 1);
    sd += __shfl_xor_sync(0xffffffffu, sd, 2);
    if ((lane & 3) == 0) { g_al1[n * HEADS + h] = sa; g_ar1[n * HEADS + h] = sd; }
}

// ---------------- fused layer-1 GAT -----------------------------------------
__global__ __launch_bounds__(256) void k_gat1(const float* __restrict__ b1) {
    int warp = threadIdx.x >> 5, lane = threadIdx.x & 31;
    int n = blockIdx.x * 8 + warp;
    if (n >= NN) return;
    int beg = g_start[n], deg = g_deg[n];
    int h = lane >> 2;
    float ard = g_ar1[n * HEADS + h];

    float mx = -1e30f;
    for (int i = (lane & 3); i < deg; i += 4) {
        int s = g_esrc[beg + i];
        mx = fmaxf(mx, lrelu(g_al1[s * HEADS + h] + ard));
    }
    mx = fmaxf(mx, __shfl_xor_sync(0xffffffffu, mx, 1));
    mx = fmaxf(mx, __shfl_xor_sync(0xffffffffu, mx, 2));

    float sum = 0.f;
    float4 acc0 = make_float4(0.f, 0.f, 0.f, 0.f);
    float4 acc1 = make_float4(0.f, 0.f, 0.f, 0.f);
    int i = 0;
    for (; i + 2 <= deg; i += 2) {
        int s0 = g_esrc[beg + i];
        int s1 = g_esrc[beg + i + 1];
        float v0 = lrelu(g_al1[s0 * HEADS + h] + ard);
        float v1 = lrelu(g_al1[s1 * HEADS + h] + ard);
        float p0 = __expf(v0 - mx);
        float p1 = __expf(v1 - mx);
        sum += p0 + p1;
        const float4* h0 = (const float4*)(g_h1 + (size_t)s0 * HD1) + lane * 2;
        const float4* h1 = (const float4*)(g_h1 + (size_t)s1 * HD1) + lane * 2;
        float4 x00 = h0[0], x01 = h0[1], x10 = h1[0], x11 = h1[1];
        acc0.x += p0 * x00.x + p1 * x10.x; acc0.y += p0 * x00.y + p1 * x10.y;
        acc0.z += p0 * x00.z + p1 * x10.z; acc0.w += p0 * x00.w + p1 * x10.w;
        acc1.x += p0 * x01.x + p1 * x11.x; acc1.y += p0 * x01.y + p1 * x11.y;
        acc1.z += p0 * x01.z + p1 * x11.z; acc1.w += p0 * x01.w + p1 * x11.w;
    }
    if (i < deg) {
        int s0 = g_esrc[beg + i];
        float v0 = lrelu(g_al1[s0 * HEADS + h] + ard);
        float p0 = __expf(v0 - mx);
        sum += p0;
        const float4* h0 = (const float4*)(g_h1 + (size_t)s0 * HD1) + lane * 2;
        float4 x00 = h0[0], x01 = h0[1];
        acc0.x += p0 * x00.x; acc0.y += p0 * x00.y; acc0.z += p0 * x00.z; acc0.w += p0 * x00.w;
        acc1.x += p0 * x01.x; acc1.y += p0 * x01.y; acc1.z += p0 * x01.z; acc1.w += p0 * x01.w;
    }
    float r = 1.f / (sum + 1e-16f);
    int c = lane * 8;
    float o[8] = {acc0.x * r, acc0.y * r, acc0.z * r, acc0.w * r,
                  acc1.x * r, acc1.y * r, acc1.z * r, acc1.w * r};
    float w[8];
    #pragma unroll
    for (int j = 0; j < 8; ++j) {
        float t = o[j] + b1[c + j];
        w[j] = t > 0.f ? t : expm1f(t);
    }
    float4* dst = (float4*)(g_h1b + (size_t)n * HD1 + c);
    dst[0] = make_float4(w[0], w[1], w[2], w[3]);
    dst[1] = make_float4(w[4], w[5], w[6], w[7]);
}

// ---------------- layer-2 attention logits ----------------------------------
__global__ __launch_bounds__(256) void k_logits2(
    const float* __restrict__ a_src, const float* __restrict__ a_dst)
{
    int warp = threadIdx.x >> 5, lane = threadIdx.x & 31;
    int n = blockIdx.x * 8 + warp;
    if (n >= NN) return;
    float2 v = ((const float2*)(g_h2 + (size_t)n * OUTC))[lane];
    int c = lane * 2;
    float sa = v.x * a_src[c] + v.y * a_src[c + 1];
    float sd = v.x * a_dst[c] + v.y * a_dst[c + 1];
    #pragma unroll
    for (int off = 16; off > 0; off >>= 1) {
        sa += __shfl_xor_sync(0xffffffffu, sa, off);
        sd += __shfl_xor_sync(0xffffffffu, sd, off);
    }
    if (lane == 0) { g_al2[n] = sa; g_ar2[n] = sd; }
}

// ---------------- fused layer-2 GAT + bias + log-softmax --------------------
__global__ __launch_bounds__(256) void k_gat2(
    const float* __restrict__ b2, float* __restrict__ out)
{
    int warp = threadIdx.x >> 5, lane = threadIdx.x & 31;
    int n = blockIdx.x * 8 + warp;
    if (n >= NN) return;
    int beg = g_start[n], deg = g_deg[n];
    float ard = g_ar2[n];

    float mx = -1e30f;
    for (int i = lane; i < deg; i += 32) {
        int s = g_esrc[beg + i];
        mx = fmaxf(mx, lrelu(g_al2[s] + ard));
    }
    #pragma unroll
    for (int off = 16; off > 0; off >>= 1)
        mx = fmaxf(mx, __shfl_xor_sync(0xffffffffu, mx, off));

    float sum = 0.f;
    float2 acc = make_float2(0.f, 0.f);
    int i = 0;
    for (; i + 2 <= deg; i += 2) {
        int s0 = g_esrc[beg + i];
        int s1 = g_esrc[beg + i + 1];
        float v0 = lrelu(g_al2[s0] + ard);
        float v1 = lrelu(g_al2[s1] + ard);
        float p0 = __expf(v0 - mx);
        float p1 = __expf(v1 - mx);
        sum += p0 + p1;
        float2 x0 = ((const float2*)(g_h2 + (size_t)s0 * OUTC))[lane];
        float2 x1 = ((const float2*)(g_h2 + (size_t)s1 * OUTC))[lane];
        acc.x += p0 * x0.x + p1 * x1.x;
        acc.y += p0 * x0.y + p1 * x1.y;
    }
    if (i < deg) {
        int s0 = g_esrc[beg + i];
        float v0 = lrelu(g_al2[s0] + ard);
        float p0 = __expf(v0 - mx);
        sum += p0;
        float2 x0 = ((const float2*)(g_h2 + (size_t)s0 * OUTC))[lane];
        acc.x += p0 * x0.x;
        acc.y += p0 * x0.y;
    }
    float r = 1.f / (sum + 1e-16f);
    int c = lane * 2;
    float v0 = acc.x * r + b2[c];
    float v1 = acc.y * r + b2[c + 1];

    float m = fmaxf(v0, v1);
    #pragma unroll
    for (int off = 16; off > 0; off >>= 1)
        m = fmaxf(m, __shfl_xor_sync(0xffffffffu, m, off));
    float ss = expf(v0 - m) + expf(v1 - m);
    #pragma unroll
    for (int off = 16; off > 0; off >>= 1)
        ss += __shfl_xor_sync(0xffffffffu, ss, off);
    float l = m + logf(ss);
    out[(size_t)n * OUTC + c]     = v0 - l;
    out[(size_t)n * OUTC + c + 1] = v1 - l;
}

// ---------------- launcher ---------------------------------------------------
extern "C" void kernel_launch(void* const* d_in, const int* in_sizes, int n_in,
                              void* d_out, int out_size)
{
    const float* x   = (const float*)d_in[0];
    const int*   ei  = (const int*)d_in[1];
    const float* W1  = (const float*)d_in[2];
    const float* a1s = (const float*)d_in[3];
    const float* a1d = (const float*)d_in[4];
    const float* b1  = (const float*)d_in[5];
    const float* W2  = (const float*)d_in[6];
    const float* a2s = (const float*)d_in[7];
    const float* a2d = (const float*)d_in[8];
    const float* b2  = (const float*)d_in[9];
    float* out = (float*)d_out;

    float *h1p, *h1bp, *h2p;
    cudaGetSymbolAddress((void**)&h1p,  g_h1);
    cudaGetSymbolAddress((void**)&h1bp, g_h1b);
    cudaGetSymbolAddress((void**)&h2p,  g_h2);

    const int EB  = (ET + 255) / 256;
    const int NB  = (NN + 255) / 256;
    const int NWB = (NN + 7) / 8;

    // launch order puts gemm1 at index 3 (ncu captures the 4th launch)
    k_zero<<<NB, 256>>>();                                     // 0
    k_hist<<<EB, 256>>>(ei);                                   // 1
    k_scanA<<<NBLK, 256>>>();                                  // 2
    dim3 g1((NN + 127) / 128, HD1 / 64);
    k_gemm_tf32<<<g1, 256>>>(x, W1, h1p, NN, FIN, HD1);        // 3  <- profiled
    k_scanC<<<NBLK, 256>>>();                                  // 4
    k_scatter<<<EB, 256>>>(ei);                                // 5
    k_logits1<<<NWB, 256>>>(a1s, a1d);                         // 6
    k_gat1<<<NWB, 256>>>(b1);                                  // 7

    dim3 g2((NN + 127) / 128, OUTC / 64);
    k_gemm_tf32<<<g2, 256>>>(h1bp, W2, h2p, NN, HD1, OUTC);    // 8
    k_logits2<<<NWB, 256>>>(a2s, a2d);                         // 9
    k_gat2<<<NWB, 256>>>(b2, out);                             // 10
}

// round 7
// speedup vs baseline: 2.4652x; 1.0309x over previous
#include <cuda_runtime.h>
#include <math.h>

#define NN    50000
#define EE    500000
#define ET    550000          // EE + NN self-loops
#define FIN   128
#define HD1   256             // HEADS*HID
#define HEADS 8
#define HID   32
#define OUTC  64
#define NBLK  196             // ceil(NN/256)

// ---------------- scratch (static device arrays; no cudaMalloc) -------------
__device__ float g_h1 [NN * HD1];    // gemm1 output
__device__ float g_h1b[NN * HD1];    // layer-1 GAT output (post bias+ELU)
__device__ float g_al1[NN * HEADS];
__device__ float g_ar1[NN * HEADS];
__device__ float g_h2 [NN * OUTC];
__device__ float g_al2[NN];
__device__ float g_ar2[NN];

__device__ int g_deg  [NN];
__device__ int g_cur  [NN];
__device__ int g_start[NN];
__device__ int g_scan [NN];
__device__ int g_bsum [256];
__device__ int g_esrc [ET];

// ---------------- helpers ---------------------------------------------------
__device__ __forceinline__ float lrelu(float v) { return v > 0.f ? v : 0.2f * v; }

__device__ __forceinline__ int edge_dst(const int* __restrict__ ei, int e) {
    return (e < EE) ? ei[EE + e] : (e - EE);
}
__device__ __forceinline__ int edge_src(const int* __restrict__ ei, int e) {
    return (e < EE) ? ei[e] : (e - EE);
}

__device__ __forceinline__ unsigned cvt_tf32(float x) {
    unsigned r; asm("cvt.rna.tf32.f32 %0, %1;" : "=r"(r) : "f"(x)); return r;
}

__device__ __forceinline__ void mma_tf32(float c[4], const unsigned a[4], const unsigned b[2]) {
    asm volatile(
        "mma.sync.aligned.m16n8k8.row.col.f32.tf32.tf32.f32 "
        "{%0,%1,%2,%3}, {%4,%5,%6,%7}, {%8,%9}, {%0,%1,%2,%3};"
        : "+f"(c[0]), "+f"(c[1]), "+f"(c[2]), "+f"(c[3])
        : "r"(a[0]), "r"(a[1]), "r"(a[2]), "r"(a[3]), "r"(b[0]), "r"(b[1]));
}

// ---------------- CSR build --------------------------------------------------
__global__ void k_zero() {
    int i = blockIdx.x * blockDim.x + threadIdx.x;
    if (i < NN) { g_deg[i] = 0; g_cur[i] = 0; }
}

__global__ void k_hist(const int* __restrict__ ei) {
    int e = blockIdx.x * blockDim.x + threadIdx.x;
    if (e >= ET) return;
    atomicAdd(&g_deg[edge_dst(ei, e)], 1);
}

__global__ void k_scanA() {
    __shared__ int s[256];
    int i = blockIdx.x * 256 + threadIdx.x;
    int v = (i < NN) ? g_deg[i] : 0;
    s[threadIdx.x] = v;
    __syncthreads();
    #pragma unroll
    for (int off = 1; off < 256; off <<= 1) {
        int t = (threadIdx.x >= off) ? s[threadIdx.x - off] : 0;
        __syncthreads();
        s[threadIdx.x] += t;
        __syncthreads();
    }
    if (i < NN) g_scan[i] = s[threadIdx.x];
    if (threadIdx.x == 255) g_bsum[blockIdx.x] = s[255];
}

__global__ void k_scanC() {
    __shared__ int red[256];
    int tid = threadIdx.x;
    red[tid] = (tid < (int)blockIdx.x) ? g_bsum[tid] : 0;
    __syncthreads();
    #pragma unroll
    for (int off = 128; off > 0; off >>= 1) {
        if (tid < off) red[tid] += red[tid + off];
        __syncthreads();
    }
    int base = red[0];
    int i = blockIdx.x * 256 + tid;
    if (i < NN) g_start[i] = g_scan[i] - g_deg[i] + base;
}

__global__ void k_scatter(const int* __restrict__ ei) {
    int e = blockIdx.x * blockDim.x + threadIdx.x;
    if (e >= ET) return;
    int d = edge_dst(ei, e);
    int pos = g_start[d] + atomicAdd(&g_cur[d], 1);
    g_esrc[pos] = edge_src(ei, e);
}

// ---------------- TF32 tensor-core GEMM: C = A[M,K] @ B[K,N] -----------------
// block 128 x BN, 256 threads. BN=128: 2m x 4n warps, warp tile 64x32 (4x4 mma).
// BN=64: 4m x 2n warps, warp tile 32x32 (2x4 mma). BK=16, interleaved-k smem
// layout so all fragment loads are LDS.64.
// k within an 8-group stored at pos = (k&3)*2 + (k>>2), so (tig, tig+4) adjacent.
template<int BN>
__global__ __launch_bounds__(256) void k_gemm_tf32(
    const float* __restrict__ A, const float* __restrict__ B, float* __restrict__ C,
    int nrows, int K, int ncols)
{
    constexpr int WN  = BN / 32;          // warps along n
    constexpr int WM  = 8 / WN;           // warps along m
    constexpr int MT  = 128 / (WM * 16);  // m16 tiles per warp
    constexpr int NT  = 4;                // n8 tiles per warp
    constexpr int ST  = 18;               // smem row stride (words), even
    constexpr int BCN = BN / 16;          // B cols per fill thread

    __shared__ __align__(16) unsigned As[128 * ST];
    __shared__ __align__(16) unsigned Bs[BN * ST];

    int tid = threadIdx.x;
    int lane = tid & 31, warp = tid >> 5;
    int g = lane >> 2, tig = lane & 3;
    int wm = warp % WM, wn = warp / WM;
    int rowBase = blockIdx.x * 128, colBase = blockIdx.y * BN;

    float c[MT][NT][4] = {};

    int ar  = tid >> 1;            // A fill: row 0..127
    int akh = (tid & 1) * 8;       // k-half 0 or 8
    int bk  = tid & 15;            // B fill: k 0..15
    int bc0 = (tid >> 4) * BCN;    // B fill: first col

    for (int kc = 0; kc < K; kc += 16) {
        // ---- fill A (interleaved k) ----
        {
            int grow = rowBase + ar;
            float4 v0 = make_float4(0.f, 0.f, 0.f, 0.f), v1 = v0;
            if (grow < nrows) {
                const float* ap = A + (size_t)grow * K + kc + akh;
                v0 = *(const float4*)ap;
                v1 = *(const float4*)(ap + 4);
            }
            float vv[8] = {v0.x, v0.y, v0.z, v0.w, v1.x, v1.y, v1.z, v1.w};
            unsigned* dst = As + ar * ST + (akh >> 3) * 8;
            #pragma unroll
            for (int j = 0; j < 8; ++j)
                dst[(j & 3) * 2 + (j >> 2)] = cvt_tf32(vv[j]);
        }
        // ---- fill B (col-major, interleaved k) ----
        {
            const float* bp = B + (size_t)(kc + bk) * ncols + colBase + bc0;
            int kpos = (bk >> 3) * 8 + (bk & 3) * 2 + ((bk >> 2) & 1);
            #pragma unroll
            for (int q = 0; q < BCN / 4; ++q) {
                float4 v = *(const float4*)(bp + q * 4);
                float vv[4] = {v.x, v.y, v.z, v.w};
                #pragma unroll
                for (int j = 0; j < 4; ++j)
                    Bs[(bc0 + q * 4 + j) * ST + kpos] = cvt_tf32(vv[j]);
            }
        }
        __syncthreads();

        #pragma unroll
        for (int ks = 0; ks < 2; ++ks) {
            unsigned a[MT][4], b[NT][2];
            #pragma unroll
            for (int mt = 0; mt < MT; ++mt) {
                int r = wm * (MT * 16) + mt * 16;
                uint2 lo = *(const uint2*)&As[(r + g)     * ST + ks * 8 + tig * 2];
                uint2 hi = *(const uint2*)&As[(r + 8 + g) * ST + ks * 8 + tig * 2];
                a[mt][0] = lo.x; a[mt][2] = lo.y;
                a[mt][1] = hi.x; a[mt][3] = hi.y;
            }
            #pragma unroll
            for (int nt = 0; nt < NT; ++nt) {
                int cn = wn * 32 + nt * 8 + g;
                uint2 bb = *(const uint2*)&Bs[cn * ST + ks * 8 + tig * 2];
                b[nt][0] = bb.x; b[nt][1] = bb.y;
            }
            #pragma unroll
            for (int mt = 0; mt < MT; ++mt)
                #pragma unroll
                for (int nt = 0; nt < NT; ++nt)
                    mma_tf32(c[mt][nt], a[mt], b[nt]);
        }
        __syncthreads();
    }

    #pragma unroll
    for (int mt = 0; mt < MT; ++mt) {
        #pragma unroll
        for (int nt = 0; nt < NT; ++nt) {
            int row0 = rowBase + wm * (MT * 16) + mt * 16 + g;
            int col  = colBase + wn * 32 + nt * 8 + tig * 2;
            if (row0 < nrows)
                *(float2*)(C + (size_t)row0 * ncols + col) = make_float2(c[mt][nt][0], c[mt][nt][1]);
            int row1 = row0 + 8;
            if (row1 < nrows)
                *(float2*)(C + (size_t)row1 * ncols + col) = make_float2(c[mt][nt][2], c[mt][nt][3]);
        }
    }
}

// ---------------- layer-1 attention logits (warp per node) ------------------
__global__ __launch_bounds__(256) void k_logits1(
    const float* __restrict__ a_src, const float* __restrict__ a_dst)
{
    int warp = threadIdx.x >> 5, lane = threadIdx.x & 31;
    int n = blockIdx.x * 8 + warp;
    if (n >= NN) return;
    const float* hrow = g_h1 + (size_t)n * HD1;
    int h = lane >> 2;
    float sa = 0.f, sd = 0.f;
    int c0 = lane * 8;
    #pragma unroll
    for (int i = 0; i < 8; ++i) {
        int c = c0 + i;
        float v = hrow[c];
        int cc = c & 31;
        sa += v * a_src[h * HID + cc];
        sd += v * a_dst[h * HID + cc];
    }
    sa += __shfl_xor_sync(0xffffffffu, sa, 1);
    sa += __shfl_xor_sync(0xffffffffu, sa, 2);
    sd += __shfl_xor_sync(0xffffffffu, sd, 1);
    sd += __shfl_xor_sync(0xffffffffu, sd, 2);
    if ((lane & 3) == 0) { g_al1[n * HEADS + h] = sa; g_ar1[n * HEADS + h] = sd; }
}

// ---------------- fused layer-1 GAT -----------------------------------------
__global__ __launch_bounds__(256) void k_gat1(const float* __restrict__ b1) {
    int warp = threadIdx.x >> 5, lane = threadIdx.x & 31;
    int n = blockIdx.x * 8 + warp;
    if (n >= NN) return;
    int beg = g_start[n], deg = g_deg[n];
    int h = lane >> 2;
    float ard = g_ar1[n * HEADS + h];

    float mx = -1e30f;
    for (int i = (lane & 3); i < deg; i += 4) {
        int s = g_esrc[beg + i];
        mx = fmaxf(mx, lrelu(g_al1[s * HEADS + h] + ard));
    }
    mx = fmaxf(mx, __shfl_xor_sync(0xffffffffu, mx, 1));
    mx = fmaxf(mx, __shfl_xor_sync(0xffffffffu, mx, 2));

    float sum = 0.f;
    float4 acc0 = make_float4(0.f, 0.f, 0.f, 0.f);
    float4 acc1 = make_float4(0.f, 0.f, 0.f, 0.f);
    int i = 0;
    for (; i + 2 <= deg; i += 2) {
        int s0 = g_esrc[beg + i];
        int s1 = g_esrc[beg + i + 1];
        float v0 = lrelu(g_al1[s0 * HEADS + h] + ard);
        float v1 = lrelu(g_al1[s1 * HEADS + h] + ard);
        float p0 = __expf(v0 - mx);
        float p1 = __expf(v1 - mx);
        sum += p0 + p1;
        const float4* h0 = (const float4*)(g_h1 + (size_t)s0 * HD1) + lane * 2;
        const float4* h1 = (const float4*)(g_h1 + (size_t)s1 * HD1) + lane * 2;
        float4 x00 = h0[0], x01 = h0[1], x10 = h1[0], x11 = h1[1];
        acc0.x += p0 * x00.x + p1 * x10.x; acc0.y += p0 * x00.y + p1 * x10.y;
        acc0.z += p0 * x00.z + p1 * x10.z; acc0.w += p0 * x00.w + p1 * x10.w;
        acc1.x += p0 * x01.x + p1 * x11.x; acc1.y += p0 * x01.y + p1 * x11.y;
        acc1.z += p0 * x01.z + p1 * x11.z; acc1.w += p0 * x01.w + p1 * x11.w;
    }
    if (i < deg) {
        int s0 = g_esrc[beg + i];
        float v0 = lrelu(g_al1[s0 * HEADS + h] + ard);
        float p0 = __expf(v0 - mx);
        sum += p0;
        const float4* h0 = (const float4*)(g_h1 + (size_t)s0 * HD1) + lane * 2;
        float4 x00 = h0[0], x01 = h0[1];
        acc0.x += p0 * x00.x; acc0.y += p0 * x00.y; acc0.z += p0 * x00.z; acc0.w += p0 * x00.w;
        acc1.x += p0 * x01.x; acc1.y += p0 * x01.y; acc1.z += p0 * x01.z; acc1.w += p0 * x01.w;
    }
    float r = 1.f / (sum + 1e-16f);
    int c = lane * 8;
    float o[8] = {acc0.x * r, acc0.y * r, acc0.z * r, acc0.w * r,
                  acc1.x * r, acc1.y * r, acc1.z * r, acc1.w * r};
    float w[8];
    #pragma unroll
    for (int j = 0; j < 8; ++j) {
        float t = o[j] + b1[c + j];
        w[j] = t > 0.f ? t : expm1f(t);
    }
    float4* dst = (float4*)(g_h1b + (size_t)n * HD1 + c);
    dst[0] = make_float4(w[0], w[1], w[2], w[3]);
    dst[1] = make_float4(w[4], w[5], w[6], w[7]);
}

// ---------------- layer-2 attention logits ----------------------------------
__global__ __launch_bounds__(256) void k_logits2(
    const float* __restrict__ a_src, const float* __restrict__ a_dst)
{
    int warp = threadIdx.x >> 5, lane = threadIdx.x & 31;
    int n = blockIdx.x * 8 + warp;
    if (n >= NN) return;
    float2 v = ((const float2*)(g_h2 + (size_t)n * OUTC))[lane];
    int c = lane * 2;
    float sa = v.x * a_src[c] + v.y * a_src[c + 1];
    float sd = v.x * a_dst[c] + v.y * a_dst[c + 1];
    #pragma unroll
    for (int off = 16; off > 0; off >>= 1) {
        sa += __shfl_xor_sync(0xffffffffu, sa, off);
        sd += __shfl_xor_sync(0xffffffffu, sd, off);
    }
    if (lane == 0) { g_al2[n] = sa; g_ar2[n] = sd; }
}

// ---------------- fused layer-2 GAT + bias + log-softmax --------------------
__global__ __launch_bounds__(256) void k_gat2(
    const float* __restrict__ b2, float* __restrict__ out)
{
    int warp = threadIdx.x >> 5, lane = threadIdx.x & 31;
    int n = blockIdx.x * 8 + warp;
    if (n >= NN) return;
    int beg = g_start[n], deg = g_deg[n];
    float ard = g_ar2[n];

    float mx = -1e30f;
    for (int i = lane; i < deg; i += 32) {
        int s = g_esrc[beg + i];
        mx = fmaxf(mx, lrelu(g_al2[s] + ard));
    }
    #pragma unroll
    for (int off = 16; off > 0; off >>= 1)
        mx = fmaxf(mx, __shfl_xor_sync(0xffffffffu, mx, off));

    float sum = 0.f;
    float2 acc = make_float2(0.f, 0.f);
    int i = 0;
    for (; i + 2 <= deg; i += 2) {
        int s0 = g_esrc[beg + i];
        int s1 = g_esrc[beg + i + 1];
        float v0 = lrelu(g_al2[s0] + ard);
        float v1 = lrelu(g_al2[s1] + ard);
        float p0 = __expf(v0 - mx);
        float p1 = __expf(v1 - mx);
        sum += p0 + p1;
        float2 x0 = ((const float2*)(g_h2 + (size_t)s0 * OUTC))[lane];
        float2 x1 = ((const float2*)(g_h2 + (size_t)s1 * OUTC))[lane];
        acc.x += p0 * x0.x + p1 * x1.x;
        acc.y += p0 * x0.y + p1 * x1.y;
    }
    if (i < deg) {
        int s0 = g_esrc[beg + i];
        float v0 = lrelu(g_al2[s0] + ard);
        float p0 = __expf(v0 - mx);
        sum += p0;
        float2 x0 = ((const float2*)(g_h2 + (size_t)s0 * OUTC))[lane];
        acc.x += p0 * x0.x;
        acc.y += p0 * x0.y;
    }
    float r = 1.f / (sum + 1e-16f);
    int c = lane * 2;
    float v0 = acc.x * r + b2[c];
    float v1 = acc.y * r + b2[c + 1];

    float m = fmaxf(v0, v1);
    #pragma unroll
    for (int off = 16; off > 0; off >>= 1)
        m = fmaxf(m, __shfl_xor_sync(0xffffffffu, m, off));
    float ss = expf(v0 - m) + expf(v1 - m);
    #pragma unroll
    for (int off = 16; off > 0; off >>= 1)
        ss += __shfl_xor_sync(0xffffffffu, ss, off);
    float l = m + logf(ss);
    out[(size_t)n * OUTC + c]     = v0 - l;
    out[(size_t)n * OUTC + c + 1] = v1 - l;
}

// ---------------- launcher ---------------------------------------------------
extern "C" void kernel_launch(void* const* d_in, const int* in_sizes, int n_in,
                              void* d_out, int out_size)
{
    const float* x   = (const float*)d_in[0];
    const int*   ei  = (const int*)d_in[1];
    const float* W1  = (const float*)d_in[2];
    const float* a1s = (const float*)d_in[3];
    const float* a1d = (const float*)d_in[4];
    const float* b1  = (const float*)d_in[5];
    const float* W2  = (const float*)d_in[6];
    const float* a2s = (const float*)d_in[7];
    const float* a2d = (const float*)d_in[8];
    const float* b2  = (const float*)d_in[9];
    float* out = (float*)d_out;

    float *h1p, *h1bp, *h2p;
    cudaGetSymbolAddress((void**)&h1p,  g_h1);
    cudaGetSymbolAddress((void**)&h1bp, g_h1b);
    cudaGetSymbolAddress((void**)&h2p,  g_h2);

    const int EB  = (ET + 255) / 256;
    const int NB  = (NN + 255) / 256;
    const int NWB = (NN + 7) / 8;

    // launch order keeps gemm1 at index 3 (ncu captures the 4th launch)
    k_zero<<<NB, 256>>>();                                       // 0
    k_hist<<<EB, 256>>>(ei);                                     // 1
    k_scanA<<<NBLK, 256>>>();                                    // 2
    dim3 g1((NN + 127) / 128, HD1 / 128);
    k_gemm_tf32<128><<<g1, 256>>>(x, W1, h1p, NN, FIN, HD1);     // 3  <- profiled
    k_scanC<<<NBLK, 256>>>();                                    // 4
    k_scatter<<<EB, 256>>>(ei);                                  // 5
    k_logits1<<<NWB, 256>>>(a1s, a1d);                           // 6
    k_gat1<<<NWB, 256>>>(b1);                                    // 7

    dim3 g2((NN + 127) / 128, OUTC / 64);
    k_gemm_tf32<64><<<g2, 256>>>(h1bp, W2, h2p, NN, HD1, OUTC);  // 8
    k_logits2<<<NWB, 256>>>(a2s, a2d);                           // 9
    k_gat2<<<NWB, 256>>>(b2, out);                               // 10
}

// round 8
// speedup vs baseline: 2.7654x; 1.1217x over previous
#include <cuda_runtime.h>
#include <cuda_fp16.h>
#include <math.h>

#define NN    50000
#define EE    500000
#define ET    550000          // EE + NN self-loops
#define FIN   128
#define HD1   256             // HEADS*HID
#define HEADS 8
#define HID   32
#define OUTC  64
#define NBLK  196             // ceil(NN/256)
#define STA   20              // As row stride (words)

// ---------------- scratch (static device arrays; no cudaMalloc) -------------
__device__ __half g_h1h[NN * HD1];   // gemm1 output (fp16)
__device__ float  g_h1b[NN * HD1];   // layer-1 GAT output (post bias+ELU)
__device__ float  g_al1[NN * HEADS];
__device__ float  g_ar1[NN * HEADS];
__device__ float  g_h2 [NN * OUTC];
__device__ float  g_al2[NN];
__device__ float  g_ar2[NN];

__device__ int g_deg  [NN];
__device__ int g_cur  [NN];
__device__ int g_start[NN];
__device__ int g_scan [NN];
__device__ int g_bsum [256];
__device__ int g_esrc [ET];

// ---------------- helpers ---------------------------------------------------
__device__ __forceinline__ float lrelu(float v) { return v > 0.f ? v : 0.2f * v; }

__device__ __forceinline__ int edge_dst(const int* __restrict__ ei, int e) {
    return (e < EE) ? ei[EE + e] : (e - EE);
}
__device__ __forceinline__ int edge_src(const int* __restrict__ ei, int e) {
    return (e < EE) ? ei[e] : (e - EE);
}

__device__ __forceinline__ unsigned cvt_tf32(float x) {
    unsigned r; asm("cvt.rna.tf32.f32 %0, %1;" : "=r"(r) : "f"(x)); return r;
}

__device__ __forceinline__ void mma_tf32(float c[4], const unsigned a[4], const unsigned b[2]) {
    asm volatile(
        "mma.sync.aligned.m16n8k8.row.col.f32.tf32.tf32.f32 "
        "{%0,%1,%2,%3}, {%4,%5,%6,%7}, {%8,%9}, {%0,%1,%2,%3};"
        : "+f"(c[0]), "+f"(c[1]), "+f"(c[2]), "+f"(c[3])
        : "r"(a[0]), "r"(a[1]), "r"(a[2]), "r"(a[3]), "r"(b[0]), "r"(b[1]));
}

// ---------------- CSR build --------------------------------------------------
__global__ void k_zero() {
    int i = blockIdx.x * blockDim.x + threadIdx.x;
    if (i < NN) { g_deg[i] = 0; g_cur[i] = 0; }
}

__global__ void k_hist(const int* __restrict__ ei) {
    int e = blockIdx.x * blockDim.x + threadIdx.x;
    if (e >= ET) return;
    atomicAdd(&g_deg[edge_dst(ei, e)], 1);
}

__global__ void k_scanA() {
    __shared__ int s[256];
    int i = blockIdx.x * 256 + threadIdx.x;
    int v = (i < NN) ? g_deg[i] : 0;
    s[threadIdx.x] = v;
    __syncthreads();
    #pragma unroll
    for (int off = 1; off < 256; off <<= 1) {
        int t = (threadIdx.x >= off) ? s[threadIdx.x - off] : 0;
        __syncthreads();
        s[threadIdx.x] += t;
        __syncthreads();
    }
    if (i < NN) g_scan[i] = s[threadIdx.x];
    if (threadIdx.x == 255) g_bsum[blockIdx.x] = s[255];
}

__global__ void k_scanC() {
    __shared__ int red[256];
    int tid = threadIdx.x;
    red[tid] = (tid < (int)blockIdx.x) ? g_bsum[tid] : 0;
    __syncthreads();
    #pragma unroll
    for (int off = 128; off > 0; off >>= 1) {
        if (tid < off) red[tid] += red[tid + off];
        __syncthreads();
    }
    int base = red[0];
    int i = blockIdx.x * 256 + tid;
    if (i < NN) g_start[i] = g_scan[i] - g_deg[i] + base;
}

__global__ void k_scatter(const int* __restrict__ ei) {
    int e = blockIdx.x * blockDim.x + threadIdx.x;
    if (e >= ET) return;
    int d = edge_dst(ei, e);
    int pos = g_start[d] + atomicAdd(&g_cur[d], 1);
    g_esrc[pos] = edge_src(ei, e);
}

// ---------------- TF32 tensor-core GEMM, B resident in smem ------------------
// block 128 x BN, 256 threads, 8 warps. Quad-k interleave: smem word
// w(k) = (k&3)*4 + (k>>2) within each 16-k chunk, so one LDS.128 per fragment
// covers both k-steps of the chunk. B slab (KK x BN) loaded once.
// HALF_OUT: write fp16 C (for h1), else fp32.
template<int BN, int KK, bool HALF_OUT>
__global__ __launch_bounds__(256, 2) void k_gemm_tf32(
    const float* __restrict__ A, const float* __restrict__ B,
    float* __restrict__ Cf, __half* __restrict__ Ch,
    int nrows, int ncols)
{
    constexpr int WN  = BN / 32;          // warps along n
    constexpr int WM  = 8 / WN;           // warps along m
    constexpr int MT  = 128 / (WM * 16);  // m16 tiles per warp
    constexpr int NT  = 4;                // n8 tiles per warp
    constexpr int STB = KK + 4;           // Bs col stride (words)
    constexpr int NC  = KK / 16;          // k chunks

    extern __shared__ unsigned sm[];
    unsigned* Bs = sm;                    // [BN][STB]
    unsigned* As = sm + BN * STB;         // [128][STA]

    int tid = threadIdx.x;
    int lane = tid & 31, warp = tid >> 5;
    int g = lane >> 2, tig = lane & 3;
    int wm = warp % WM, wn = warp / WM;
    int rowBase = blockIdx.x * 128, colBase = blockIdx.y * BN;

    // ---- fill B slab once (coalesced LDG, vectorized STS) ----
    {
        int tig_f = tid >> 6;     // 0..3
        int cc    = tid & 63;
        #pragma unroll
        for (int c16 = 0; c16 < NC; ++c16) {
            #pragma unroll
            for (int hb = 0; hb < BN / 64; ++hb) {
                int col = cc + hb * 64;
                const float* bp = B + (size_t)(c16 * 16 + tig_f) * ncols + colBase + col;
                unsigned w0 = cvt_tf32(bp[0]);
                unsigned w1 = cvt_tf32(bp[(size_t)4 * ncols]);
                unsigned w2 = cvt_tf32(bp[(size_t)8 * ncols]);
                unsigned w3 = cvt_tf32(bp[(size_t)12 * ncols]);
                *(uint4*)&Bs[col * STB + c16 * 16 + tig_f * 4] = make_uint4(w0, w1, w2, w3);
            }
        }
    }

    float c[MT][NT][4] = {};

    int tig_a = tid & 3, rr = tid >> 2;   // A fill: 2 rows (rr, rr+64), quad k
    float av[2][4];

    // prefetch chunk 0
    #pragma unroll
    for (int r = 0; r < 2; ++r) {
        int grow = rowBase + rr + r * 64;
        #pragma unroll
        for (int j = 0; j < 4; ++j)
            av[r][j] = (grow < nrows) ? A[(size_t)grow * KK + tig_a + 4 * j] : 0.f;
    }

    for (int kci = 0; kci < NC; ++kci) {
        // store prefetched A chunk (STS.128, interleaved layout)
        #pragma unroll
        for (int r = 0; r < 2; ++r)
            *(uint4*)&As[(rr + r * 64) * STA + tig_a * 4] =
                make_uint4(cvt_tf32(av[r][0]), cvt_tf32(av[r][1]),
                           cvt_tf32(av[r][2]), cvt_tf32(av[r][3]));
        __syncthreads();

        // prefetch next chunk while computing
        if (kci + 1 < NC) {
            int kc = (kci + 1) * 16;
            #pragma unroll
            for (int r = 0; r < 2; ++r) {
                int grow = rowBase + rr + r * 64;
                #pragma unroll
                for (int j = 0; j < 4; ++j)
                    av[r][j] = (grow < nrows) ? A[(size_t)grow * KK + kc + tig_a + 4 * j] : 0.f;
            }
        }

        // fragments: one LDS.128 covers both k-steps
        unsigned a0[MT][4], a1[MT][4], b0[NT][2], b1[NT][2];
        #pragma unroll
        for (int mt = 0; mt < MT; ++mt) {
            int rlo = wm * (MT * 16) + mt * 16 + g;
            uint4 ag = *(const uint4*)&As[rlo * STA + tig * 4];
            uint4 ah = *(const uint4*)&As[(rlo + 8) * STA + tig * 4];
            a0[mt][0] = ag.x; a0[mt][1] = ah.x; a0[mt][2] = ag.y; a0[mt][3] = ah.y;
            a1[mt][0] = ag.z; a1[mt][1] = ah.z; a1[mt][2] = ag.w; a1[mt][3] = ah.w;
        }
        #pragma unroll
        for (int nt = 0; nt < NT; ++nt) {
            int cn = wn * 32 + nt * 8 + g;
            uint4 bb = *(const uint4*)&Bs[cn * STB + kci * 16 + tig * 4];
            b0[nt][0] = bb.x; b0[nt][1] = bb.y;
            b1[nt][0] = bb.z; b1[nt][1] = bb.w;
        }
        #pragma unroll
        for (int mt = 0; mt < MT; ++mt)
            #pragma unroll
            for (int nt = 0; nt < NT; ++nt) {
                mma_tf32(c[mt][nt], a0[mt], b0[nt]);
                mma_tf32(c[mt][nt], a1[mt], b1[nt]);
            }
        __syncthreads();
    }

    // epilogue
    #pragma unroll
    for (int mt = 0; mt < MT; ++mt) {
        #pragma unroll
        for (int nt = 0; nt < NT; ++nt) {
            int row0 = rowBase + wm * (MT * 16) + mt * 16 + g;
            int row1 = row0 + 8;
            int col  = colBase + wn * 32 + nt * 8 + tig * 2;
            if (HALF_OUT) {
                if (row0 < nrows)
                    *(__half2*)(Ch + (size_t)row0 * ncols + col) =
                        __floats2half2_rn(c[mt][nt][0], c[mt][nt][1]);
                if (row1 < nrows)
                    *(__half2*)(Ch + (size_t)row1 * ncols + col) =
                        __floats2half2_rn(c[mt][nt][2], c[mt][nt][3]);
            } else {
                if (row0 < nrows)
                    *(float2*)(Cf + (size_t)row0 * ncols + col) =
                        make_float2(c[mt][nt][0], c[mt][nt][1]);
                if (row1 < nrows)
                    *(float2*)(Cf + (size_t)row1 * ncols + col) =
                        make_float2(c[mt][nt][2], c[mt][nt][3]);
            }
        }
    }
}

// ---------------- layer-1 attention logits (warp per node, fp16 h1) ---------
__global__ __launch_bounds__(256) void k_logits1(
    const float* __restrict__ a_src, const float* __restrict__ a_dst)
{
    int warp = threadIdx.x >> 5, lane = threadIdx.x & 31;
    int n = blockIdx.x * 8 + warp;
    if (n >= NN) return;
    int h = lane >> 2;
    int c0 = lane * 8;
    uint4 q = *(const uint4*)(g_h1h + (size_t)n * HD1 + c0);
    const __half2* hh = (const __half2*)&q;
    float v[8];
    #pragma unroll
    for (int p = 0; p < 4; ++p) {
        float2 f = __half22float2(hh[p]);
        v[2 * p] = f.x; v[2 * p + 1] = f.y;
    }
    float sa = 0.f, sd = 0.f;
    #pragma unroll
    for (int i = 0; i < 8; ++i) {
        int cc = (c0 + i) & 31;
        sa += v[i] * a_src[h * HID + cc];
        sd += v[i] * a_dst[h * HID + cc];
    }
    sa += __shfl_xor_sync(0xffffffffu, sa, 1);
    sa += __shfl_xor_sync(0xffffffffu, sa, 2);
    sd += __shfl_xor_sync(0xffffffffu, sd, 1);
    sd += __shfl_xor_sync(0xffffffffu, sd, 2);
    if ((lane & 3) == 0) { g_al1[n * HEADS + h] = sa; g_ar1[n * HEADS + h] = sd; }
}

// ---------------- fused layer-1 GAT (fp16 message gather) --------------------
__global__ __launch_bounds__(256) void k_gat1(const float* __restrict__ b1) {
    int warp = threadIdx.x >> 5, lane = threadIdx.x & 31;
    int n = blockIdx.x * 8 + warp;
    if (n >= NN) return;
    int beg = g_start[n], deg = g_deg[n];
    int h = lane >> 2;
    float ard = g_ar1[n * HEADS + h];

    float mx = -1e30f;
    for (int i = (lane & 3); i < deg; i += 4) {
        int s = g_esrc[beg + i];
        mx = fmaxf(mx, lrelu(g_al1[s * HEADS + h] + ard));
    }
    mx = fmaxf(mx, __shfl_xor_sync(0xffffffffu, mx, 1));
    mx = fmaxf(mx, __shfl_xor_sync(0xffffffffu, mx, 2));

    float sum = 0.f;
    float acc[8] = {};
    int i = 0;
    for (; i + 2 <= deg; i += 2) {
        int s0 = g_esrc[beg + i];
        int s1 = g_esrc[beg + i + 1];
        float p0 = __expf(lrelu(g_al1[s0 * HEADS + h] + ard) - mx);
        float p1 = __expf(lrelu(g_al1[s1 * HEADS + h] + ard) - mx);
        sum += p0 + p1;
        uint4 q0 = *((const uint4*)(g_h1h + (size_t)s0 * HD1) + lane);
        uint4 q1 = *((const uint4*)(g_h1h + (size_t)s1 * HD1) + lane);
        const __half2* h0 = (const __half2*)&q0;
        const __half2* h1 = (const __half2*)&q1;
        #pragma unroll
        for (int p = 0; p < 4; ++p) {
            float2 f0 = __half22float2(h0[p]);
            float2 f1 = __half22float2(h1[p]);
            acc[2 * p]     += p0 * f0.x + p1 * f1.x;
            acc[2 * p + 1] += p0 * f0.y + p1 * f1.y;
        }
    }
    if (i < deg) {
        int s0 = g_esrc[beg + i];
        float p0 = __expf(lrelu(g_al1[s0 * HEADS + h] + ard) - mx);
        sum += p0;
        uint4 q0 = *((const uint4*)(g_h1h + (size_t)s0 * HD1) + lane);
        const __half2* h0 = (const __half2*)&q0;
        #pragma unroll
        for (int p = 0; p < 4; ++p) {
            float2 f0 = __half22float2(h0[p]);
            acc[2 * p]     += p0 * f0.x;
            acc[2 * p + 1] += p0 * f0.y;
        }
    }
    float r = 1.f / (sum + 1e-16f);
    int c = lane * 8;
    float w[8];
    #pragma unroll
    for (int j = 0; j < 8; ++j) {
        float t = acc[j] * r + b1[c + j];
        w[j] = t > 0.f ? t : expm1f(t);
    }
    float4* dst = (float4*)(g_h1b + (size_t)n * HD1 + c);
    dst[0] = make_float4(w[0], w[1], w[2], w[3]);
    dst[1] = make_float4(w[4], w[5], w[6], w[7]);
}

// ---------------- layer-2 attention logits ----------------------------------
__global__ __launch_bounds__(256) void k_logits2(
    const float* __restrict__ a_src, const float* __restrict__ a_dst)
{
    int warp = threadIdx.x >> 5, lane = threadIdx.x & 31;
    int n = blockIdx.x * 8 + warp;
    if (n >= NN) return;
    float2 v = ((const float2*)(g_h2 + (size_t)n * OUTC))[lane];
    int c = lane * 2;
    float sa = v.x * a_src[c] + v.y * a_src[c + 1];
    float sd = v.x * a_dst[c] + v.y * a_dst[c + 1];
    #pragma unroll
    for (int off = 16; off > 0; off >>= 1) {
        sa += __shfl_xor_sync(0xffffffffu, sa, off);
        sd += __shfl_xor_sync(0xffffffffu, sd, off);
    }
    if (lane == 0) { g_al2[n] = sa; g_ar2[n] = sd; }
}

// ---------------- fused layer-2 GAT + bias + log-softmax --------------------
__global__ __launch_bounds__(256) void k_gat2(
    const float* __restrict__ b2, float* __restrict__ out)
{
    int warp = threadIdx.x >> 5, lane = threadIdx.x & 31;
    int n = blockIdx.x * 8 + warp;
    if (n >= NN) return;
    int beg = g_start[n], deg = g_deg[n];
    float ard = g_ar2[n];

    float mx = -1e30f;
    for (int i = lane; i < deg; i += 32) {
        int s = g_esrc[beg + i];
        mx = fmaxf(mx, lrelu(g_al2[s] + ard));
    }
    #pragma unroll
    for (int off = 16; off > 0; off >>= 1)
        mx = fmaxf(mx, __shfl_xor_sync(0xffffffffu, mx, off));

    float sum = 0.f;
    float2 acc = make_float2(0.f, 0.f);
    int i = 0;
    for (; i + 2 <= deg; i += 2) {
        int s0 = g_esrc[beg + i];
        int s1 = g_esrc[beg + i + 1];
        float p0 = __expf(lrelu(g_al2[s0] + ard) - mx);
        float p1 = __expf(lrelu(g_al2[s1] + ard) - mx);
        sum += p0 + p1;
        float2 x0 = ((const float2*)(g_h2 + (size_t)s0 * OUTC))[lane];
        float2 x1 = ((const float2*)(g_h2 + (size_t)s1 * OUTC))[lane];
        acc.x += p0 * x0.x + p1 * x1.x;
        acc.y += p0 * x0.y + p1 * x1.y;
    }
    if (i < deg) {
        int s0 = g_esrc[beg + i];
        float p0 = __expf(lrelu(g_al2[s0] + ard) - mx);
        sum += p0;
        float2 x0 = ((const float2*)(g_h2 + (size_t)s0 * OUTC))[lane];
        acc.x += p0 * x0.x;
        acc.y += p0 * x0.y;
    }
    float r = 1.f / (sum + 1e-16f);
    int c = lane * 2;
    float v0 = acc.x * r + b2[c];
    float v1 = acc.y * r + b2[c + 1];

    float m = fmaxf(v0, v1);
    #pragma unroll
    for (int off = 16; off > 0; off >>= 1)
        m = fmaxf(m, __shfl_xor_sync(0xffffffffu, m, off));
    float ss = expf(v0 - m) + expf(v1 - m);
    #pragma unroll
    for (int off = 16; off > 0; off >>= 1)
        ss += __shfl_xor_sync(0xffffffffu, ss, off);
    float l = m + logf(ss);
    out[(size_t)n * OUTC + c]     = v0 - l;
    out[(size_t)n * OUTC + c + 1] = v1 - l;
}

// ---------------- launcher ---------------------------------------------------
extern "C" void kernel_launch(void* const* d_in, const int* in_sizes, int n_in,
                              void* d_out, int out_size)
{
    const float* x   = (const float*)d_in[0];
    const int*   ei  = (const int*)d_in[1];
    const float* W1  = (const float*)d_in[2];
    const float* a1s = (const float*)d_in[3];
    const float* a1d = (const float*)d_in[4];
    const float* b1  = (const float*)d_in[5];
    const float* W2  = (const float*)d_in[6];
    const float* a2s = (const float*)d_in[7];
    const float* a2d = (const float*)d_in[8];
    const float* b2  = (const float*)d_in[9];
    float* out = (float*)d_out;

    __half* h1hp; float *h1bp, *h2p;
    cudaGetSymbolAddress((void**)&h1hp, g_h1h);
    cudaGetSymbolAddress((void**)&h1bp, g_h1b);
    cudaGetSymbolAddress((void**)&h2p,  g_h2);

    const int EB  = (ET + 255) / 256;
    const int NB  = (NN + 255) / 256;
    const int NWB = (NN + 7) / 8;

    const int SM1 = (128 * STA + 128 * (128 + 4)) * 4;   // 77824 B
    const int SM2 = (128 * STA + 64 * (256 + 4)) * 4;    // 76800 B
    cudaFuncSetAttribute(k_gemm_tf32<128, 128, true>,
                         cudaFuncAttributeMaxDynamicSharedMemorySize, SM1);
    cudaFuncSetAttribute(k_gemm_tf32<64, 256, false>,
                         cudaFuncAttributeMaxDynamicSharedMemorySize, SM2);

    // launch order keeps gemm1 at index 3 (ncu captures the 4th launch)
    k_zero<<<NB, 256>>>();                                       // 0
    k_hist<<<EB, 256>>>(ei);                                     // 1
    k_scanA<<<NBLK, 256>>>();                                    // 2
    dim3 g1((NN + 127) / 128, HD1 / 128);
    k_gemm_tf32<128, 128, true><<<g1, 256, SM1>>>(x, W1, nullptr, h1hp, NN, HD1);  // 3
    k_scanC<<<NBLK, 256>>>();                                    // 4
    k_scatter<<<EB, 256>>>(ei);                                  // 5
    k_logits1<<<NWB, 256>>>(a1s, a1d);                           // 6
    k_gat1<<<NWB, 256>>>(b1);                                    // 7

    dim3 g2((NN + 127) / 128, 1);
    k_gemm_tf32<64, 256, false><<<g2, 256, SM2>>>(h1bp, W2, h2p, nullptr, NN, OUTC); // 8
    k_logits2<<<NWB, 256>>>(a2s, a2d);                           // 9
    k_gat2<<<NWB, 256>>>(b2, out);                               // 10
}